// round 1
// baseline (speedup 1.0000x reference)
#include <cuda_runtime.h>
#include <cstdint>

#define N_SRC0 120000
#define N_DST0 40000
#define N_DST1 10000
#define T_REL  5
#define HID    128
#define IN_DIM 256
#define OUT_DIM 153
#define E0 800000
#define E1 300000
#define NEG_SLOPE 0.2f
#define EPS_LN 1e-5f

// ---------------- static device scratch (no allocations allowed) ----------------
__device__ __align__(128) float g_Hs0[(size_t)T_REL * N_SRC0 * HID]; // 307 MB
__device__ __align__(128) float g_Hs1[(size_t)T_REL * N_DST0 * HID]; // 102 MB
__device__ __align__(16)  float g_el0[(size_t)T_REL * N_SRC0 * 4];
__device__ __align__(16)  float g_er0[(size_t)T_REL * N_DST0 * 4];
__device__ __align__(16)  float g_el1[(size_t)T_REL * N_DST0 * 4];
__device__ __align__(16)  float g_er1[(size_t)T_REL * N_DST1 * 4];
__device__ __align__(128) float g_acc0[(size_t)N_DST0 * HID];
__device__ __align__(128) float g_h0[(size_t)N_DST0 * HID];
__device__ __align__(128) float g_acc1[(size_t)N_DST1 * HID];
__device__ __align__(128) float g_h1[(size_t)N_DST1 * HID];
__device__ __align__(128) float g_mlp[(size_t)N_DST1 * HID];
__device__ int      g_cnt[T_REL * N_DST0];
__device__ int      g_offs[T_REL * (N_DST0 + 1)];
__device__ int      g_cur[T_REL * N_DST0];
__device__ int      g_eperm[T_REL * E0];
__device__ unsigned g_menc[(size_t)T_REL * N_DST0 * 4];
__device__ double   g_colsum[HID];
__device__ double   g_colsq[HID];
__device__ float    g_mean[HID];
__device__ float    g_rstd[HID];

// ---------------- helpers ----------------
__device__ __forceinline__ unsigned enc_f(float f) {
    unsigned u = __float_as_uint(f);
    return (u & 0x80000000u) ? ~u : (u | 0x80000000u);
}
__device__ __forceinline__ float dec_f(unsigned e) {
    return (e & 0x80000000u) ? __uint_as_float(e ^ 0x80000000u)
                             : __uint_as_float(~e);
}
#define ENC_NEG_INF 0x007FFFFFu  // enc(-inf)

// ---------------- SGEMM: C = A @ B (+bias). 128x128x8, 256 thr, 8x8/thread ----
// REL: blockIdx.y = relation j; B_j = B + j*K*128; C_j = C + j*M*128 (ldc=128).
template<bool REL, bool HASBIAS>
__global__ void __launch_bounds__(256) sgemm_kernel(
    const float* __restrict__ A, const float* __restrict__ B,
    const float* __restrict__ bias, float* __restrict__ C,
    int M, int N, int K)
{
    int ldc, bn0;
    if (REL) {
        int j = blockIdx.y;
        B += (size_t)j * K * HID;
        C += (size_t)j * M * HID;
        bn0 = 0; ldc = HID; N = HID;
    } else {
        bn0 = blockIdx.y * 128; ldc = N;
    }
    int bm0 = blockIdx.x * 128;

    __shared__ __align__(16) float As[8][128];
    __shared__ __align__(16) float Bs[8][128];

    int tid = threadIdx.x;
    int tx = tid & 15, ty = tid >> 4;

    float acc[8][8];
#pragma unroll
    for (int i = 0; i < 8; i++)
#pragma unroll
        for (int j2 = 0; j2 < 8; j2++) acc[i][j2] = 0.f;

    int a_row = tid >> 1;          // 0..127
    int a_col = (tid & 1) << 2;    // 0 or 4
    int b_row = tid >> 5;          // 0..7
    int b_col = (tid & 31) << 2;   // 0..124

    for (int k0 = 0; k0 < K; k0 += 8) {
        int gm = bm0 + a_row;
        float4 av = make_float4(0.f, 0.f, 0.f, 0.f);
        if (gm < M) av = *(const float4*)(A + (size_t)gm * K + (k0 + a_col));
        As[a_col + 0][a_row] = av.x; As[a_col + 1][a_row] = av.y;
        As[a_col + 2][a_row] = av.z; As[a_col + 3][a_row] = av.w;

        if (REL) {
            float4 bv = *(const float4*)(B + (size_t)(k0 + b_row) * HID + b_col);
            Bs[b_row][b_col + 0] = bv.x; Bs[b_row][b_col + 1] = bv.y;
            Bs[b_row][b_col + 2] = bv.z; Bs[b_row][b_col + 3] = bv.w;
        } else {
#pragma unroll
            for (int q = 0; q < 4; q++) {
                int gn = bn0 + b_col + q;
                Bs[b_row][b_col + q] = (gn < N) ? B[(size_t)(k0 + b_row) * N + gn] : 0.f;
            }
        }
        __syncthreads();
#pragma unroll
        for (int kk = 0; kk < 8; kk++) {
            float4 a0 = *(const float4*)&As[kk][ty * 4];
            float4 a1 = *(const float4*)&As[kk][64 + ty * 4];
            float4 b0 = *(const float4*)&Bs[kk][tx * 4];
            float4 b1 = *(const float4*)&Bs[kk][64 + tx * 4];
            float ra[8] = {a0.x, a0.y, a0.z, a0.w, a1.x, a1.y, a1.z, a1.w};
            float rb[8] = {b0.x, b0.y, b0.z, b0.w, b1.x, b1.y, b1.z, b1.w};
#pragma unroll
            for (int i = 0; i < 8; i++)
#pragma unroll
                for (int j2 = 0; j2 < 8; j2++) acc[i][j2] += ra[i] * rb[j2];
        }
        __syncthreads();
    }
#pragma unroll
    for (int i = 0; i < 8; i++) {
        int gm = bm0 + ((i < 4) ? (ty * 4 + i) : (64 + ty * 4 + i - 4));
        if (gm >= M) continue;
#pragma unroll
        for (int j2 = 0; j2 < 8; j2++) {
            int gn = bn0 + ((j2 < 4) ? (tx * 4 + j2) : (64 + tx * 4 + j2 - 4));
            if (!REL && gn >= N) continue;
            float v = acc[i][j2];
            if (HASBIAS) v += bias[gn];
            C[(size_t)gm * ldc + gn] = v;
        }
    }
}

// ---------------- attention logits: ev[j][i][h] = sum_d Hs[j][i][h*32+d]*alpha[j][h][d]
__global__ void attn_logits_kernel(const float* __restrict__ Hs, int hsrows,
                                   const float* __restrict__ alpha,
                                   float* __restrict__ ev, int nout)
{
    int j = blockIdx.y;
    int warp = threadIdx.x >> 5, lane = threadIdx.x & 31;
    int i = blockIdx.x * 4 + warp;
    if (i >= nout) return;
    const float* row = Hs + ((size_t)j * hsrows + i) * HID;
    float4 v = *(const float4*)(row + lane * 4);
    float4 a = *(const float4*)(alpha + (size_t)j * HID + lane * 4);
    float p = v.x * a.x + v.y * a.y + v.z * a.z + v.w * a.w;
    p += __shfl_xor_sync(0xffffffffu, p, 1);
    p += __shfl_xor_sync(0xffffffffu, p, 2);
    p += __shfl_xor_sync(0xffffffffu, p, 4);
    if ((lane & 7) == 0)
        ev[((size_t)j * nout + i) * 4 + (lane >> 3)] = p;
}

// ---------------- CSR build ----------------
__global__ void fill_int_kernel(int* p, int n, int v) {
    int i = blockIdx.x * blockDim.x + threadIdx.x;
    if (i < n) p[i] = v;
}
__global__ void fill_uint_kernel(unsigned* p, int n, unsigned v) {
    int i = blockIdx.x * blockDim.x + threadIdx.x;
    if (i < n) p[i] = v;
}
__global__ void copy_int_kernel(const int* a, int* b, int n) {
    int i = blockIdx.x * blockDim.x + threadIdx.x;
    if (i < n) b[i] = a[i];
}
__global__ void hist_kernel(const int* __restrict__ dst, int E, int* __restrict__ cnt) {
    int e = blockIdx.x * blockDim.x + threadIdx.x;
    if (e < E) atomicAdd(&cnt[dst[e]], 1);
}
// single-block exclusive scan, blockDim = 1024
__global__ void scan_kernel(const int* __restrict__ cnt, int* __restrict__ offs, int n) {
    __shared__ int wsum[32];
    __shared__ int running_s;
    if (threadIdx.x == 0) running_s = 0;
    __syncthreads();
    int lane = threadIdx.x & 31, wid = threadIdx.x >> 5;
    for (int base = 0; base < n; base += 1024) {
        int i = base + (int)threadIdx.x;
        int v = (i < n) ? cnt[i] : 0;
        int x = v;
#pragma unroll
        for (int d = 1; d < 32; d <<= 1) {
            int t = __shfl_up_sync(0xffffffffu, x, d);
            if (lane >= d) x += t;
        }
        if (lane == 31) wsum[wid] = x;
        __syncthreads();
        if (wid == 0) {
            int y = wsum[lane];
#pragma unroll
            for (int d = 1; d < 32; d <<= 1) {
                int t = __shfl_up_sync(0xffffffffu, y, d);
                if (lane >= d) y += t;
            }
            wsum[lane] = y;
        }
        __syncthreads();
        int incl = x + (wid ? wsum[wid - 1] : 0);
        int r = running_s;
        if (i < n) offs[i] = r + (incl - v);
        int total = wsum[31];
        __syncthreads();
        if (threadIdx.x == 0) running_s = r + total;
        __syncthreads();
    }
    if (threadIdx.x == 0) offs[n] = running_s;
}
__global__ void scatter_kernel(const int* __restrict__ dst, int E,
                               int* __restrict__ cur, int* __restrict__ eperm) {
    int e = blockIdx.x * blockDim.x + threadIdx.x;
    if (e < E) {
        int pos = atomicAdd(&cur[dst[e]], 1);
        eperm[pos] = e;
    }
}

// ---------------- edge max pass (per relation) ----------------
__global__ void edge_max_kernel(const int* __restrict__ src, const int* __restrict__ dst,
                                const float* __restrict__ el, const float* __restrict__ er,
                                unsigned* __restrict__ menc, int E)
{
    int e = blockIdx.x * blockDim.x + threadIdx.x;
    if (e >= E) return;
    int s = src[e], d = dst[e];
    float4 L = *(const float4*)(el + (size_t)s * 4);
    float4 R = *(const float4*)(er + (size_t)d * 4);
    float lv[4] = {L.x, L.y, L.z, L.w};
    float rv[4] = {R.x, R.y, R.z, R.w};
#pragma unroll
    for (int h = 0; h < 4; h++) {
        float v = lv[h] + rv[h];
        v = v > 0.f ? v : NEG_SLOPE * v;
        atomicMax(&menc[(size_t)d * 4 + h], enc_f(v));
    }
}

// ---------------- aggregation: one block (128 thr) per dst node ----------------
__global__ void aggregate_kernel(
    const float* __restrict__ Hs, const float* __restrict__ el,
    const float* __restrict__ er, const unsigned* __restrict__ menc,
    const int* __restrict__ offs, const int* __restrict__ eperm,
    const int* __restrict__ srcArr, const float* __restrict__ brow,
    float* __restrict__ out)
{
    int nd = blockIdx.x;
    int t = threadIdx.x;
    int h = t >> 5;
    int o0 = offs[nd], o1 = offs[nd + 1];
    int cnt = o1 - o0;
    float bb = brow[t];
    size_t obase = (size_t)nd * HID + t;
    if (cnt == 0) { out[obase] += bb; return; }

    float m_all[4], er_all[4];
    {
        float4 e4 = *(const float4*)(er + (size_t)nd * 4);
        er_all[0] = e4.x; er_all[1] = e4.y; er_all[2] = e4.z; er_all[3] = e4.w;
        uint4 m4 = *(const uint4*)(menc + (size_t)nd * 4);
        m_all[0] = dec_f(m4.x); m_all[1] = dec_f(m4.y);
        m_all[2] = dec_f(m4.z); m_all[3] = dec_f(m4.w);
    }
    __shared__ int   s_src[128];
    __shared__ float s_w[4][128];
    float acc = 0.f, ssum = 0.f;
    for (int c0 = 0; c0 < cnt; c0 += 128) {
        int k = c0 + t;
        if (k < cnt) {
            int e = eperm[o0 + k];
            int s = srcArr[e];
            s_src[t] = s;
            float4 L = *(const float4*)(el + (size_t)s * 4);
            float lv[4] = {L.x, L.y, L.z, L.w};
#pragma unroll
            for (int hh = 0; hh < 4; hh++) {
                float v = lv[hh] + er_all[hh];
                v = v > 0.f ? v : NEG_SLOPE * v;
                s_w[hh][t] = __expf(v - m_all[hh]);
            }
        }
        __syncthreads();
        int len = min(128, cnt - c0);
        const float* wrow = s_w[h];
#pragma unroll 4
        for (int k2 = 0; k2 < len; k2++) {
            float w = wrow[k2];
            float x = Hs[(size_t)s_src[k2] * HID + t];
            acc += w * x;
            ssum += w;
        }
        __syncthreads();
    }
    out[obase] += acc / ssum + bb;
}

// ---------------- column norm (mean/var over rows) + activation ----------------
__global__ void colstat_zero_kernel() {
    int t = threadIdx.x;
    g_colsum[t] = 0.0; g_colsq[t] = 0.0;
}
__global__ void colstat_partial_kernel(const float* __restrict__ X, int nrows) {
    int t = threadIdx.x;   // feature, blockDim = 128
    int r0 = blockIdx.x * 256;
    int r1 = min(r0 + 256, nrows);
    float fs = 0.f, fq = 0.f;
    for (int r = r0; r < r1; r++) {
        float v = X[(size_t)r * HID + t];
        fs += v; fq += v * v;
    }
    atomicAdd(&g_colsum[t], (double)fs);
    atomicAdd(&g_colsq[t], (double)fq);
}
__global__ void colstat_final_kernel(int nrows) {
    int t = threadIdx.x;
    double inv = 1.0 / (double)nrows;
    double mean = g_colsum[t] * inv;
    double var = g_colsq[t] * inv - mean * mean;
    g_mean[t] = (float)mean;
    g_rstd[t] = (float)(1.0 / sqrt(var + (double)EPS_LN));
}
// act: 0 = elu, 1 = relu
__global__ void norm_act_kernel(const float* __restrict__ X, const float* __restrict__ g,
                                const float* __restrict__ be, float* __restrict__ Y,
                                int nrows, int act)
{
    int idx = blockIdx.x * blockDim.x + threadIdx.x;
    if (idx >= nrows * HID) return;
    int t = idx & (HID - 1);
    float v = (X[idx] - g_mean[t]) * g_rstd[t] * g[t] + be[t];
    if (act) v = v > 0.f ? v : 0.f;
    else     v = v > 0.f ? v : expm1f(v);
    Y[idx] = v;
}

// ---------------- host orchestration ----------------
static inline void* sym(const void* s) { void* p = nullptr; cudaGetSymbolAddress(&p, s); return p; }

static void run_layer(const float* X, int n_src, int n_dst, int Kdim,
                      const float* W, const float* alpha_l, const float* alpha_r,
                      const float* b, const float* Ws, const float* bs,
                      const float* gamma, const float* beta,
                      const int* srcAll, const int* dstAll, int E,
                      float* Hs, float* elbuf, float* erbuf,
                      float* accbuf, float* hout)
{
    int* cnt = (int*)sym(g_cnt);
    int* offs = (int*)sym(g_offs);
    int* cur = (int*)sym(g_cur);
    int* eperm = (int*)sym(g_eperm);
    unsigned* menc = (unsigned*)sym(g_menc);

    {   // Hs = X @ W[j], all relations
        dim3 grid((n_src + 127) / 128, T_REL);
        sgemm_kernel<true, false><<<grid, 256>>>(X, W, nullptr, Hs, n_src, HID, Kdim);
    }
    {   // acc = X[:n_dst] @ Ws + bs
        dim3 grid((n_dst + 127) / 128, 1);
        sgemm_kernel<false, true><<<grid, 256>>>(X, Ws, bs, accbuf, n_dst, HID, Kdim);
    }
    {   dim3 grid((n_src + 3) / 4, T_REL);
        attn_logits_kernel<<<grid, 128>>>(Hs, n_src, alpha_l, elbuf, n_src); }
    {   dim3 grid((n_dst + 3) / 4, T_REL);
        attn_logits_kernel<<<grid, 128>>>(Hs, n_src, alpha_r, erbuf, n_dst); }

    for (int j = 0; j < T_REL; j++) {
        const int* sj = srcAll + (size_t)j * E;
        const int* dj = dstAll + (size_t)j * E;
        float* Hj = Hs + (size_t)j * n_src * HID;
        const float* elj = elbuf + (size_t)j * n_src * 4;
        const float* erj = erbuf + (size_t)j * n_dst * 4;
        int* cntj = cnt + j * N_DST0;
        int* offj = offs + j * (N_DST0 + 1);
        int* curj = cur + j * N_DST0;
        int* epj = eperm + (size_t)j * E0;
        unsigned* mj = menc + (size_t)j * N_DST0 * 4;

        fill_int_kernel<<<(n_dst + 255) / 256, 256>>>(cntj, n_dst, 0);
        hist_kernel<<<(E + 255) / 256, 256>>>(dj, E, cntj);
        scan_kernel<<<1, 1024>>>(cntj, offj, n_dst);
        copy_int_kernel<<<(n_dst + 255) / 256, 256>>>(offj, curj, n_dst);
        scatter_kernel<<<(E + 255) / 256, 256>>>(dj, E, curj, epj);
        fill_uint_kernel<<<(n_dst * 4 + 255) / 256, 256>>>(mj, n_dst * 4, ENC_NEG_INF);
        edge_max_kernel<<<(E + 255) / 256, 256>>>(sj, dj, elj, erj, mj, E);
        aggregate_kernel<<<n_dst, 128>>>(Hj, elj, erj, mj, offj, epj, sj,
                                         b + (size_t)j * HID, accbuf);
    }
    colstat_zero_kernel<<<1, 128>>>();
    colstat_partial_kernel<<<(n_dst + 255) / 256, 128>>>(accbuf, n_dst);
    colstat_final_kernel<<<1, 128>>>(n_dst);
    norm_act_kernel<<<(n_dst * HID + 255) / 256, 256>>>(accbuf, gamma, beta, hout, n_dst, 0);
}

extern "C" void kernel_launch(void* const* d_in, const int* in_sizes, int n_in,
                              void* d_out, int out_size)
{
    (void)in_sizes; (void)n_in; (void)out_size;
    const float* x   = (const float*)d_in[0];
    const float* W0  = (const float*)d_in[1];
    const float* al0 = (const float*)d_in[2];
    const float* ar0 = (const float*)d_in[3];
    const float* b0  = (const float*)d_in[4];
    const float* Ws0 = (const float*)d_in[5];
    const float* bs0 = (const float*)d_in[6];
    const float* g0  = (const float*)d_in[7];
    const float* be0 = (const float*)d_in[8];
    const float* W1  = (const float*)d_in[9];
    const float* al1 = (const float*)d_in[10];
    const float* ar1 = (const float*)d_in[11];
    const float* b1  = (const float*)d_in[12];
    const float* Ws1 = (const float*)d_in[13];
    const float* bs1 = (const float*)d_in[14];
    const float* g1  = (const float*)d_in[15];
    const float* be1 = (const float*)d_in[16];
    const float* Wm1 = (const float*)d_in[17];
    const float* bm1 = (const float*)d_in[18];
    const float* gm  = (const float*)d_in[19];
    const float* bem = (const float*)d_in[20];
    const float* Wm2 = (const float*)d_in[21];
    const float* bm2 = (const float*)d_in[22];
    const int* src0  = (const int*)d_in[23];
    const int* dst0  = (const int*)d_in[24];
    const int* src1  = (const int*)d_in[25];
    const int* dst1  = (const int*)d_in[26];
    float* out = (float*)d_out;

    float* Hs0  = (float*)sym(g_Hs0);
    float* Hs1  = (float*)sym(g_Hs1);
    float* el0p = (float*)sym(g_el0);
    float* er0p = (float*)sym(g_er0);
    float* el1p = (float*)sym(g_el1);
    float* er1p = (float*)sym(g_er1);
    float* acc0 = (float*)sym(g_acc0);
    float* h0   = (float*)sym(g_h0);
    float* acc1 = (float*)sym(g_acc1);
    float* h1   = (float*)sym(g_h1);
    float* mlp  = (float*)sym(g_mlp);

    // Layer 0: x[120000,256] -> h0[40000,128]
    run_layer(x, N_SRC0, N_DST0, IN_DIM, W0, al0, ar0, b0, Ws0, bs0, g0, be0,
              src0, dst0, E0, Hs0, el0p, er0p, acc0, h0);

    // Layer 1: h0[40000,128] -> h1[10000,128]
    run_layer(h0, N_DST0, N_DST1, HID, W1, al1, ar1, b1, Ws1, bs1, g1, be1,
              src1, dst1, E1, Hs1, el1p, er1p, acc1, h1);

    // MLP
    {
        dim3 grid((N_DST1 + 127) / 128, 1);
        sgemm_kernel<false, true><<<grid, 256>>>(h1, Wm1, bm1, mlp, N_DST1, HID, HID);
    }
    colstat_zero_kernel<<<1, 128>>>();
    colstat_partial_kernel<<<(N_DST1 + 255) / 256, 128>>>(mlp, N_DST1);
    colstat_final_kernel<<<1, 128>>>(N_DST1);
    norm_act_kernel<<<(N_DST1 * HID + 255) / 256, 256>>>(mlp, gm, bem, mlp, N_DST1, 1);
    {
        dim3 grid((N_DST1 + 127) / 128, (OUT_DIM + 127) / 128);
        sgemm_kernel<false, true><<<grid, 256>>>(mlp, Wm2, bm2, out, N_DST1, OUT_DIM, HID);
    }
}

// round 3
// speedup vs baseline: 1.2896x; 1.2896x over previous
#include <cuda_runtime.h>
#include <cuda_bf16.h>
#include <cstdint>

#define N_SRC0 120000
#define N_DST0 40000
#define N_DST1 10000
#define T_REL  5
#define HID    128
#define IN_DIM 256
#define OUT_DIM 153
#define E0 800000
#define E1 300000
#define NEG_SLOPE 0.2f
#define EPS_LN 1e-5f

typedef __nv_bfloat16 bf16;

// ---------------- static device scratch ----------------
__device__ __align__(128) float g_Hs0[(size_t)T_REL * N_SRC0 * HID];
__device__ __align__(128) float g_Hs1[(size_t)T_REL * N_DST0 * HID];
__device__ __align__(16)  float g_el0[(size_t)T_REL * N_SRC0 * 4];
__device__ __align__(16)  float g_er0[(size_t)T_REL * N_DST0 * 4];
__device__ __align__(16)  float g_el1[(size_t)T_REL * N_DST0 * 4];
__device__ __align__(16)  float g_er1[(size_t)T_REL * N_DST1 * 4];
__device__ __align__(128) float g_acc0[(size_t)N_DST0 * HID];
__device__ __align__(128) float g_h0[(size_t)N_DST0 * HID];
__device__ __align__(128) float g_acc1[(size_t)N_DST1 * HID];
__device__ __align__(128) float g_h1[(size_t)N_DST1 * HID];
__device__ __align__(128) float g_mlp[(size_t)N_DST1 * HID];
__device__ int      g_cnt[T_REL * N_DST0];
__device__ int      g_offs[T_REL * (N_DST0 + 1)];
__device__ int      g_cur[T_REL * N_DST0];
__device__ int      g_eperm[T_REL * E0];
__device__ unsigned g_menc[(size_t)T_REL * N_DST0 * 4];
__device__ double   g_colsum[HID];
__device__ double   g_colsq[HID];
__device__ float    g_mean[HID];
__device__ float    g_rstd[HID];
// bf16 split buffers
__device__ __align__(128) bf16 g_xhi[(size_t)N_SRC0 * IN_DIM];
__device__ __align__(128) bf16 g_xlo[(size_t)N_SRC0 * IN_DIM];
__device__ __align__(128) bf16 g_shi[(size_t)N_DST0 * HID];
__device__ __align__(128) bf16 g_slo[(size_t)N_DST0 * HID];
// transposed split weights, packed
#define W0T_OFF   0
#define WS0T_OFF  163840
#define W1T_OFF   196608
#define WS1T_OFF  278528
#define WM1T_OFF  294912
#define WM2T_OFF  311296
#define WT_TOTAL  330880
__device__ __align__(128) bf16 g_wthi[WT_TOTAL];
__device__ __align__(128) bf16 g_wtlo[WT_TOTAL];

// ---------------- helpers ----------------
__device__ __forceinline__ unsigned enc_f(float f) {
    unsigned u = __float_as_uint(f);
    return (u & 0x80000000u) ? ~u : (u | 0x80000000u);
}
__device__ __forceinline__ float dec_f(unsigned e) {
    return (e & 0x80000000u) ? __uint_as_float(e ^ 0x80000000u)
                             : __uint_as_float(~e);
}
#define ENC_NEG_INF 0x007FFFFFu

__device__ __forceinline__ void cp_async16(uint32_t dst, const void* src, int sz) {
    asm volatile("cp.async.cg.shared.global [%0], [%1], 16, %2;\n"
                 :: "r"(dst), "l"(src), "r"(sz));
}
__device__ __forceinline__ void cp_commit() {
    asm volatile("cp.async.commit_group;\n");
}
__device__ __forceinline__ void ldsm4(uint32_t* r, uint32_t addr) {
    asm volatile("ldmatrix.sync.aligned.m8n8.x4.shared.b16 {%0,%1,%2,%3}, [%4];"
        : "=r"(r[0]), "=r"(r[1]), "=r"(r[2]), "=r"(r[3]) : "r"(addr));
}
__device__ __forceinline__ void mma16816(float* c, const uint32_t* a, uint32_t b0, uint32_t b1) {
    asm volatile("mma.sync.aligned.m16n8k16.row.col.f32.bf16.bf16.f32 "
        "{%0,%1,%2,%3}, {%4,%5,%6,%7}, {%8,%9}, {%0,%1,%2,%3};"
        : "+f"(c[0]), "+f"(c[1]), "+f"(c[2]), "+f"(c[3])
        : "r"(a[0]), "r"(a[1]), "r"(a[2]), "r"(a[3]), "r"(b0), "r"(b1));
}

// ---------------- split kernels ----------------
__global__ void split_kernel(const float* __restrict__ X, bf16* __restrict__ hi,
                             bf16* __restrict__ lo, size_t n)
{
    size_t i = (size_t)blockIdx.x * blockDim.x + threadIdx.x;
    if (i >= n) return;
    float v = X[i];
    bf16 h = __float2bfloat16(v);
    hi[i] = h;
    lo[i] = __float2bfloat16(v - __bfloat162float(h));
}
// W: [j][K][N] fp32 -> out [j][N][K] bf16 (hi/lo)
__global__ void splitw_kernel(const float* __restrict__ W, bf16* __restrict__ hiT,
                              bf16* __restrict__ loT, int K, int N)
{
    int j = blockIdx.y;
    int idx = blockIdx.x * blockDim.x + threadIdx.x;
    if (idx >= N * K) return;
    int n = idx / K, k = idx - n * K;
    float v = W[((size_t)j * K + k) * N + n];
    bf16 h = __float2bfloat16(v);
    hiT[(size_t)j * N * K + idx] = h;
    loT[(size_t)j * N * K + idx] = __float2bfloat16(v - __bfloat162float(h));
}

// ---------------- bf16x3 MMA GEMM: C = A@W (+bias), fp32-accurate ----------------
// A split (hi/lo) [M][K] bf16; W transposed split [N][K] bf16.
// REL: blockIdx.y = j; B += j*128*K; C += j*M*128.
#define GSTRIDE 40
template<bool REL, bool HASBIAS>
__global__ void __launch_bounds__(256) mma_gemm_kernel(
    const bf16* __restrict__ Ahi, const bf16* __restrict__ Alo,
    const bf16* __restrict__ BThi, const bf16* __restrict__ BTlo,
    const float* __restrict__ bias, float* __restrict__ C,
    int M, int N, int K)
{
    __shared__ bf16 As[2][128][GSTRIDE];
    __shared__ bf16 Bs[2][128][GSTRIDE];

    int bm0 = blockIdx.x * 128;
    int bn0, ldc;
    if (REL) {
        int j = blockIdx.y;
        BThi += (size_t)j * 128 * K;
        BTlo += (size_t)j * 128 * K;
        C    += (size_t)j * M * 128;
        bn0 = 0; ldc = 128; N = 128;
    } else { bn0 = blockIdx.y * 128; ldc = N; }

    int tid = threadIdx.x, lane = tid & 31, warp = tid >> 5;
    int wm = (warp & 3) * 32, wn = (warp >> 2) * 64;

    const bf16* APs[3] = {Ahi, Alo, Ahi};
    const bf16* BPs[3] = {BThi, BThi, BTlo};
    int kc = K >> 5;
    int NIT = 3 * kc;

    int ldrow = tid >> 2;
    int ldcol = (tid & 3) << 3;

    uint32_t sA0 = (uint32_t)__cvta_generic_to_shared(&As[0][0][0]);
    uint32_t sB0 = (uint32_t)__cvta_generic_to_shared(&Bs[0][0][0]);
    const uint32_t stagesz = 128 * GSTRIDE * 2;

    int mrowA = lane & 15, mcolA = (lane >> 4) << 3;
    int mrowB = (lane & 7) | ((lane >> 4) << 3);
    int mcolB = ((lane >> 3) & 1) << 3;

    float acc[2][8][4];
#pragma unroll
    for (int a = 0; a < 2; a++)
#pragma unroll
        for (int b = 0; b < 8; b++)
#pragma unroll
            for (int c = 0; c < 4; c++) acc[a][b][c] = 0.f;

#define LOAD_STAGE(IT, ST) do {                                               \
    int p_ = (IT) / kc;                                                       \
    int kk_ = ((IT) - p_ * kc) << 5;                                          \
    const bf16* Ap_ = APs[p_];                                                \
    const bf16* Bp_ = BPs[p_];                                                \
    _Pragma("unroll")                                                         \
    for (int hh = 0; hh < 2; hh++) {                                          \
        int row = ldrow + hh * 64;                                            \
        int gm = bm0 + row;                                                   \
        int ok = gm < M;                                                      \
        const bf16* src = Ap_ + (size_t)(ok ? gm : 0) * K + kk_ + ldcol;      \
        cp_async16(sA0 + (ST) * stagesz + (row * GSTRIDE + ldcol) * 2, src, ok ? 16 : 0); \
    }                                                                         \
    _Pragma("unroll")                                                         \
    for (int hh = 0; hh < 2; hh++) {                                          \
        int row = ldrow + hh * 64;                                            \
        int gn = bn0 + row;                                                   \
        int ok = gn < N;                                                      \
        const bf16* src = Bp_ + (size_t)(ok ? gn : 0) * K + kk_ + ldcol;      \
        cp_async16(sB0 + (ST) * stagesz + (row * GSTRIDE + ldcol) * 2, src, ok ? 16 : 0); \
    }                                                                         \
    cp_commit();                                                              \
} while (0)

    LOAD_STAGE(0, 0);

    for (int it = 0; it < NIT; it++) {
        int st = it & 1;
        if (it + 1 < NIT) {
            LOAD_STAGE(it + 1, st ^ 1);
            asm volatile("cp.async.wait_group 1;\n" ::: "memory");
        } else {
            asm volatile("cp.async.wait_group 0;\n" ::: "memory");
        }
        __syncthreads();

        uint32_t aBase = sA0 + st * stagesz;
        uint32_t bBase = sB0 + st * stagesz;
#pragma unroll
        for (int s = 0; s < 2; s++) {
            uint32_t a[2][4];
#pragma unroll
            for (int mt = 0; mt < 2; mt++)
                ldsm4(a[mt], aBase + ((wm + mt * 16 + mrowA) * GSTRIDE + s * 16 + mcolA) * 2);
            uint32_t b[4][4];
#pragma unroll
            for (int np = 0; np < 4; np++)
                ldsm4(b[np], bBase + ((wn + np * 16 + mrowB) * GSTRIDE + s * 16 + mcolB) * 2);
#pragma unroll
            for (int mt = 0; mt < 2; mt++)
#pragma unroll
                for (int np = 0; np < 4; np++) {
                    mma16816(acc[mt][2 * np],     a[mt], b[np][0], b[np][1]);
                    mma16816(acc[mt][2 * np + 1], a[mt], b[np][2], b[np][3]);
                }
        }
        __syncthreads();
    }
#undef LOAD_STAGE

    int trow = lane >> 2, tcol = (lane & 3) << 1;
#pragma unroll
    for (int mt = 0; mt < 2; mt++) {
#pragma unroll
        for (int nt = 0; nt < 8; nt++) {
            int gn = bn0 + wn + nt * 8 + tcol;
            bool okn0 = REL || (gn < N);
            bool okn1 = REL || (gn + 1 < N);
            float b0a = 0.f, b1a = 0.f;
            if (HASBIAS) {
                if (okn0) b0a = bias[gn];
                if (okn1) b1a = bias[gn + 1];
            }
            int gm0 = bm0 + wm + mt * 16 + trow;
            int gm1 = gm0 + 8;
            float* cr = acc[mt][nt];
            if (gm0 < M) {
                if (okn0) C[(size_t)gm0 * ldc + gn]     = cr[0] + b0a;
                if (okn1) C[(size_t)gm0 * ldc + gn + 1] = cr[1] + b1a;
            }
            if (gm1 < M) {
                if (okn0) C[(size_t)gm1 * ldc + gn]     = cr[2] + b0a;
                if (okn1) C[(size_t)gm1 * ldc + gn + 1] = cr[3] + b1a;
            }
        }
    }
}

// ---------------- attention logits ----------------
__global__ void attn_logits_kernel(const float* __restrict__ Hs, int hsrows,
                                   const float* __restrict__ alpha,
                                   float* __restrict__ ev, int nout)
{
    int j = blockIdx.y;
    int warp = threadIdx.x >> 5, lane = threadIdx.x & 31;
    int i = blockIdx.x * 4 + warp;
    if (i >= nout) return;
    const float* row = Hs + ((size_t)j * hsrows + i) * HID;
    float4 v = *(const float4*)(row + lane * 4);
    float4 a = *(const float4*)(alpha + (size_t)j * HID + lane * 4);
    float p = v.x * a.x + v.y * a.y + v.z * a.z + v.w * a.w;
    p += __shfl_xor_sync(0xffffffffu, p, 1);
    p += __shfl_xor_sync(0xffffffffu, p, 2);
    p += __shfl_xor_sync(0xffffffffu, p, 4);
    if ((lane & 7) == 0)
        ev[((size_t)j * nout + i) * 4 + (lane >> 3)] = p;
}

// ---------------- CSR build (batched over relations) ----------------
__global__ void fill_int_kernel(int* p, int n, int v) {
    int i = blockIdx.x * blockDim.x + threadIdx.x;
    if (i < n) p[i] = v;
}
__global__ void fill_uint_kernel(unsigned* p, int n, unsigned v) {
    int i = blockIdx.x * blockDim.x + threadIdx.x;
    if (i < n) p[i] = v;
}
__global__ void hist_kernel(const int* __restrict__ dstAll, int E, int* __restrict__ cnt) {
    int j = blockIdx.y;
    int e = blockIdx.x * blockDim.x + threadIdx.x;
    if (e < E) atomicAdd(&cnt[j * N_DST0 + dstAll[(size_t)j * E + e]], 1);
}
__global__ void scan_kernel(const int* __restrict__ cntAll, int* __restrict__ offsAll, int n) {
    const int* cnt = cntAll + blockIdx.x * N_DST0;
    int* offs = offsAll + blockIdx.x * (N_DST0 + 1);
    __shared__ int wsum[32];
    __shared__ int running_s;
    if (threadIdx.x == 0) running_s = 0;
    __syncthreads();
    int lane = threadIdx.x & 31, wid = threadIdx.x >> 5;
    for (int base = 0; base < n; base += 1024) {
        int i = base + (int)threadIdx.x;
        int v = (i < n) ? cnt[i] : 0;
        int x = v;
#pragma unroll
        for (int d = 1; d < 32; d <<= 1) {
            int t = __shfl_up_sync(0xffffffffu, x, d);
            if (lane >= d) x += t;
        }
        if (lane == 31) wsum[wid] = x;
        __syncthreads();
        if (wid == 0) {
            int y = wsum[lane];
#pragma unroll
            for (int d = 1; d < 32; d <<= 1) {
                int t = __shfl_up_sync(0xffffffffu, y, d);
                if (lane >= d) y += t;
            }
            wsum[lane] = y;
        }
        __syncthreads();
        int incl = x + (wid ? wsum[wid - 1] : 0);
        int r = running_s;
        if (i < n) offs[i] = r + (incl - v);
        int total = wsum[31];
        __syncthreads();
        if (threadIdx.x == 0) running_s = r + total;
        __syncthreads();
    }
    if (threadIdx.x == 0) offs[n] = running_s;
}
__global__ void copy_off_kernel(const int* __restrict__ offs, int* __restrict__ cur, int n) {
    int j = blockIdx.y;
    int i = blockIdx.x * blockDim.x + threadIdx.x;
    if (i < n) cur[j * N_DST0 + i] = offs[j * (N_DST0 + 1) + i];
}
__global__ void scatter_kernel(const int* __restrict__ dstAll, int E,
                               int* __restrict__ cur, int* __restrict__ eperm) {
    int j = blockIdx.y;
    int e = blockIdx.x * blockDim.x + threadIdx.x;
    if (e < E) {
        int pos = atomicAdd(&cur[j * N_DST0 + dstAll[(size_t)j * E + e]], 1);
        eperm[(size_t)j * E0 + pos] = e;
    }
}
__global__ void edge_max_kernel(const int* __restrict__ srcAll, const int* __restrict__ dstAll,
                                const float* __restrict__ el, const float* __restrict__ er,
                                unsigned* __restrict__ menc, int E, int n_src, int n_dst)
{
    int j = blockIdx.y;
    int e = blockIdx.x * blockDim.x + threadIdx.x;
    if (e >= E) return;
    int s = srcAll[(size_t)j * E + e], d = dstAll[(size_t)j * E + e];
    float4 L = *(const float4*)(el + ((size_t)j * n_src + s) * 4);
    float4 R = *(const float4*)(er + ((size_t)j * n_dst + d) * 4);
    float lv[4] = {L.x, L.y, L.z, L.w};
    float rv[4] = {R.x, R.y, R.z, R.w};
    unsigned* mj = menc + (size_t)j * N_DST0 * 4;
#pragma unroll
    for (int h = 0; h < 4; h++) {
        float v = lv[h] + rv[h];
        v = v > 0.f ? v : NEG_SLOPE * v;
        atomicMax(&mj[(size_t)d * 4 + h], enc_f(v));
    }
}

// ---------------- aggregation: one block per dst node, all relations ----------------
__global__ void aggregate_all_kernel(
    const float* __restrict__ Hs, int hsrows,
    const float* __restrict__ el, const float* __restrict__ er,
    const unsigned* __restrict__ menc,
    const int* __restrict__ offs, const int* __restrict__ eperm,
    const int* __restrict__ srcAll, int E,
    const float* __restrict__ b, int n_dst, float* __restrict__ out)
{
    int nd = blockIdx.x;
    int t = threadIdx.x;
    int h = t >> 5;
    __shared__ int   s_src[128];
    __shared__ float s_w[4][128];
    float total = 0.f;

    for (int j = 0; j < T_REL; j++) {
        const float* Hj  = Hs + (size_t)j * hsrows * HID;
        const float* elj = el + (size_t)j * hsrows * 4;
        const float* erj = er + (size_t)j * n_dst * 4;
        const unsigned* mj = menc + (size_t)j * N_DST0 * 4;
        const int* offj = offs + j * (N_DST0 + 1);
        const int* epj  = eperm + (size_t)j * E0;
        const int* sj   = srcAll + (size_t)j * E;

        total += b[j * HID + t];
        int o0 = offj[nd], o1 = offj[nd + 1];
        int cnt = o1 - o0;
        if (cnt == 0) continue;

        float m_all[4], er_all[4];
        {
            float4 e4 = *(const float4*)(erj + (size_t)nd * 4);
            er_all[0] = e4.x; er_all[1] = e4.y; er_all[2] = e4.z; er_all[3] = e4.w;
            uint4 m4 = *(const uint4*)(mj + (size_t)nd * 4);
            m_all[0] = dec_f(m4.x); m_all[1] = dec_f(m4.y);
            m_all[2] = dec_f(m4.z); m_all[3] = dec_f(m4.w);
        }
        float acc = 0.f, ssum = 0.f;
        for (int c0 = 0; c0 < cnt; c0 += 128) {
            int k = c0 + t;
            if (k < cnt) {
                int e = epj[o0 + k];
                int s = sj[e];
                s_src[t] = s;
                float4 L = *(const float4*)(elj + (size_t)s * 4);
                float lv[4] = {L.x, L.y, L.z, L.w};
#pragma unroll
                for (int hh = 0; hh < 4; hh++) {
                    float v = lv[hh] + er_all[hh];
                    v = v > 0.f ? v : NEG_SLOPE * v;
                    s_w[hh][t] = __expf(v - m_all[hh]);
                }
            }
            __syncthreads();
            int len = min(128, cnt - c0);
            const float* wrow = s_w[h];
#pragma unroll 4
            for (int k2 = 0; k2 < len; k2++) {
                float w = wrow[k2];
                float x = Hj[(size_t)s_src[k2] * HID + t];
                acc += w * x;
                ssum += w;
            }
            __syncthreads();
        }
        total += acc / ssum;
    }
    out[(size_t)nd * HID + t] += total;
}

// ---------------- column norm + activation ----------------
__global__ void colstat_zero_kernel() {
    int t = threadIdx.x;
    g_colsum[t] = 0.0; g_colsq[t] = 0.0;
}
__global__ void colstat_partial_kernel(const float* __restrict__ X, int nrows) {
    int t = threadIdx.x;
    int r0 = blockIdx.x * 256;
    int r1 = min(r0 + 256, nrows);
    float fs = 0.f, fq = 0.f;
    for (int r = r0; r < r1; r++) {
        float v = X[(size_t)r * HID + t];
        fs += v; fq += v * v;
    }
    atomicAdd(&g_colsum[t], (double)fs);
    atomicAdd(&g_colsq[t], (double)fq);
}
__global__ void colstat_final_kernel(int nrows) {
    int t = threadIdx.x;
    double inv = 1.0 / (double)nrows;
    double mean = g_colsum[t] * inv;
    double var = g_colsq[t] * inv - mean * mean;
    g_mean[t] = (float)mean;
    g_rstd[t] = (float)(1.0 / sqrt(var + (double)EPS_LN));
}
__global__ void norm_act_kernel(const float* __restrict__ X, const float* __restrict__ g,
                                const float* __restrict__ be, float* __restrict__ Y,
                                int nrows, int act)
{
    int idx = blockIdx.x * blockDim.x + threadIdx.x;
    if (idx >= nrows * HID) return;
    int t = idx & (HID - 1);
    float v = (X[idx] - g_mean[t]) * g_rstd[t] * g[t] + be[t];
    if (act) v = v > 0.f ? v : 0.f;
    else     v = v > 0.f ? v : expm1f(v);
    Y[idx] = v;
}

// ---------------- host orchestration ----------------
static inline void* sym(const void* s) { void* p = nullptr; cudaGetSymbolAddress(&p, s); return p; }

static void run_layer(const bf16* Ahi, const bf16* Alo, int n_src, int n_dst, int Kdim,
                      const bf16* WtHi, const bf16* WtLo,
                      const bf16* WsHi, const bf16* WsLo,
                      const float* alpha_l, const float* alpha_r,
                      const float* b, const float* bs,
                      const float* gamma, const float* beta,
                      const int* srcAll, const int* dstAll, int E,
                      float* Hs, float* elbuf, float* erbuf,
                      float* accbuf, float* hout)
{
    int* cnt = (int*)sym(g_cnt);
    int* offs = (int*)sym(g_offs);
    int* cur = (int*)sym(g_cur);
    int* eperm = (int*)sym(g_eperm);
    unsigned* menc = (unsigned*)sym(g_menc);

    {   // Hs = A @ W[j], all relations
        dim3 grid((n_src + 127) / 128, T_REL);
        mma_gemm_kernel<true, false><<<grid, 256>>>(Ahi, Alo, WtHi, WtLo, nullptr, Hs,
                                                    n_src, HID, Kdim);
    }
    {   // acc = A[:n_dst] @ Ws + bs
        dim3 grid((n_dst + 127) / 128, 1);
        mma_gemm_kernel<false, true><<<grid, 256>>>(Ahi, Alo, WsHi, WsLo, bs, accbuf,
                                                    n_dst, HID, Kdim);
    }
    {   dim3 grid((n_src + 3) / 4, T_REL);
        attn_logits_kernel<<<grid, 128>>>(Hs, n_src, alpha_l, elbuf, n_src); }
    {   dim3 grid((n_dst + 3) / 4, T_REL);
        attn_logits_kernel<<<grid, 128>>>(Hs, n_src, alpha_r, erbuf, n_dst); }

    // CSR build (batched across relations)
    fill_int_kernel<<<(T_REL * N_DST0 + 255) / 256, 256>>>(cnt, T_REL * N_DST0, 0);
    { dim3 grid((E + 255) / 256, T_REL);
      hist_kernel<<<grid, 256>>>(dstAll, E, cnt); }
    scan_kernel<<<T_REL, 1024>>>(cnt, offs, n_dst);
    { dim3 grid((n_dst + 255) / 256, T_REL);
      copy_off_kernel<<<grid, 256>>>(offs, cur, n_dst); }
    { dim3 grid((E + 255) / 256, T_REL);
      scatter_kernel<<<grid, 256>>>(dstAll, E, cur, eperm); }
    fill_uint_kernel<<<(T_REL * N_DST0 * 4 + 255) / 256, 256>>>(menc, T_REL * N_DST0 * 4, ENC_NEG_INF);
    { dim3 grid((E + 255) / 256, T_REL);
      edge_max_kernel<<<grid, 256>>>(srcAll, dstAll, elbuf, erbuf, menc, E, n_src, n_dst); }

    aggregate_all_kernel<<<n_dst, 128>>>(Hs, n_src, elbuf, erbuf, menc, offs, eperm,
                                         srcAll, E, b, n_dst, accbuf);

    colstat_zero_kernel<<<1, 128>>>();
    colstat_partial_kernel<<<(n_dst + 255) / 256, 128>>>(accbuf, n_dst);
    colstat_final_kernel<<<1, 128>>>(n_dst);
    norm_act_kernel<<<(n_dst * HID + 255) / 256, 256>>>(accbuf, gamma, beta, hout, n_dst, 0);
}

extern "C" void kernel_launch(void* const* d_in, const int* in_sizes, int n_in,
                              void* d_out, int out_size)
{
    (void)in_sizes; (void)n_in; (void)out_size;
    const float* x   = (const float*)d_in[0];
    const float* W0  = (const float*)d_in[1];
    const float* al0 = (const float*)d_in[2];
    const float* ar0 = (const float*)d_in[3];
    const float* b0  = (const float*)d_in[4];
    const float* Ws0 = (const float*)d_in[5];
    const float* bs0 = (const float*)d_in[6];
    const float* g0  = (const float*)d_in[7];
    const float* be0 = (const float*)d_in[8];
    const float* W1  = (const float*)d_in[9];
    const float* al1 = (const float*)d_in[10];
    const float* ar1 = (const float*)d_in[11];
    const float* b1  = (const float*)d_in[12];
    const float* Ws1 = (const float*)d_in[13];
    const float* bs1 = (const float*)d_in[14];
    const float* g1  = (const float*)d_in[15];
    const float* be1 = (const float*)d_in[16];
    const float* Wm1 = (const float*)d_in[17];
    const float* bm1 = (const float*)d_in[18];
    const float* gm  = (const float*)d_in[19];
    const float* bem = (const float*)d_in[20];
    const float* Wm2 = (const float*)d_in[21];
    const float* bm2 = (const float*)d_in[22];
    const int* src0  = (const int*)d_in[23];
    const int* dst0  = (const int*)d_in[24];
    const int* src1  = (const int*)d_in[25];
    const int* dst1  = (const int*)d_in[26];
    float* out = (float*)d_out;

    float* Hs0  = (float*)sym(g_Hs0);
    float* Hs1  = (float*)sym(g_Hs1);
    float* el0p = (float*)sym(g_el0);
    float* er0p = (float*)sym(g_er0);
    float* el1p = (float*)sym(g_el1);
    float* er1p = (float*)sym(g_er1);
    float* acc0 = (float*)sym(g_acc0);
    float* h0   = (float*)sym(g_h0);
    float* acc1 = (float*)sym(g_acc1);
    float* h1   = (float*)sym(g_h1);
    float* mlp  = (float*)sym(g_mlp);
    bf16* xhi = (bf16*)sym(g_xhi);
    bf16* xlo = (bf16*)sym(g_xlo);
    bf16* shi = (bf16*)sym(g_shi);
    bf16* slo = (bf16*)sym(g_slo);
    bf16* wthi = (bf16*)sym(g_wthi);
    bf16* wtlo = (bf16*)sym(g_wtlo);

    // ---- weight prep: transpose + bf16 split ----
    { dim3 g((HID * IN_DIM + 255) / 256, T_REL);
      splitw_kernel<<<g, 256>>>(W0, wthi + W0T_OFF, wtlo + W0T_OFF, IN_DIM, HID); }
    { dim3 g((HID * IN_DIM + 255) / 256, 1);
      splitw_kernel<<<g, 256>>>(Ws0, wthi + WS0T_OFF, wtlo + WS0T_OFF, IN_DIM, HID); }
    { dim3 g((HID * HID + 255) / 256, T_REL);
      splitw_kernel<<<g, 256>>>(W1, wthi + W1T_OFF, wtlo + W1T_OFF, HID, HID); }
    { dim3 g((HID * HID + 255) / 256, 1);
      splitw_kernel<<<g, 256>>>(Ws1, wthi + WS1T_OFF, wtlo + WS1T_OFF, HID, HID); }
    { dim3 g((HID * HID + 255) / 256, 1);
      splitw_kernel<<<g, 256>>>(Wm1, wthi + WM1T_OFF, wtlo + WM1T_OFF, HID, HID); }
    { dim3 g((OUT_DIM * HID + 255) / 256, 1);
      splitw_kernel<<<g, 256>>>(Wm2, wthi + WM2T_OFF, wtlo + WM2T_OFF, HID, OUT_DIM); }

    // ---- split x ----
    {
        size_t n = (size_t)N_SRC0 * IN_DIM;
        split_kernel<<<(unsigned)((n + 255) / 256), 256>>>(x, xhi, xlo, n);
    }

    // ---- Layer 0 ----
    run_layer(xhi, xlo, N_SRC0, N_DST0, IN_DIM,
              wthi + W0T_OFF, wtlo + W0T_OFF, wthi + WS0T_OFF, wtlo + WS0T_OFF,
              al0, ar0, b0, bs0, g0, be0,
              src0, dst0, E0, Hs0, el0p, er0p, acc0, h0);

    // split h0
    {
        size_t n = (size_t)N_DST0 * HID;
        split_kernel<<<(unsigned)((n + 255) / 256), 256>>>(h0, shi, slo, n);
    }

    // ---- Layer 1 ----
    run_layer(shi, slo, N_DST0, N_DST1, HID,
              wthi + W1T_OFF, wtlo + W1T_OFF, wthi + WS1T_OFF, wtlo + WS1T_OFF,
              al1, ar1, b1, bs1, g1, be1,
              src1, dst1, E1, Hs1, el1p, er1p, acc1, h1);

    // split h1 (reuse shi/slo)
    {
        size_t n = (size_t)N_DST1 * HID;
        split_kernel<<<(unsigned)((n + 255) / 256), 256>>>(h1, shi, slo, n);
    }

    // ---- MLP ----
    {
        dim3 grid((N_DST1 + 127) / 128, 1);
        mma_gemm_kernel<false, true><<<grid, 256>>>(shi, slo, wthi + WM1T_OFF, wtlo + WM1T_OFF,
                                                    bm1, mlp, N_DST1, HID, HID);
    }
    colstat_zero_kernel<<<1, 128>>>();
    colstat_partial_kernel<<<(N_DST1 + 255) / 256, 128>>>(mlp, N_DST1);
    colstat_final_kernel<<<1, 128>>>(N_DST1);
    norm_act_kernel<<<(N_DST1 * HID + 255) / 256, 256>>>(mlp, gm, bem, mlp, N_DST1, 1);
    // split relu output (reuse shi/slo)
    {
        size_t n = (size_t)N_DST1 * HID;
        split_kernel<<<(unsigned)((n + 255) / 256), 256>>>(mlp, shi, slo, n);
    }
    {
        dim3 grid((N_DST1 + 127) / 128, (OUT_DIM + 127) / 128);
        mma_gemm_kernel<false, true><<<grid, 256>>>(shi, slo, wthi + WM2T_OFF, wtlo + WM2T_OFF,
                                                    bm2, out, N_DST1, OUT_DIM, HID);
    }
}

// round 4
// speedup vs baseline: 1.5137x; 1.1738x over previous
#include <cuda_runtime.h>
#include <cuda_bf16.h>
#include <cstdint>

#define N_SRC0 120000
#define N_DST0 40000
#define N_DST1 10000
#define T_REL  5
#define HID    128
#define IN_DIM 256
#define OUT_DIM 153
#define E0 800000
#define E1 300000
#define NEG_SLOPE 0.2f
#define EPS_LN 1e-5f

typedef __nv_bfloat16 bf16;

// ---------------- static device scratch ----------------
__device__ __align__(128) float g_Hs0[(size_t)T_REL * N_SRC0 * HID];
__device__ __align__(128) float g_Hs1[(size_t)T_REL * N_DST0 * HID];
__device__ __align__(16)  float g_el0[(size_t)T_REL * N_SRC0 * 4];
__device__ __align__(16)  float g_er0[(size_t)T_REL * N_DST0 * 4];
__device__ __align__(16)  float g_el1[(size_t)T_REL * N_DST0 * 4];
__device__ __align__(16)  float g_er1[(size_t)T_REL * N_DST1 * 4];
__device__ __align__(128) float g_acc0[(size_t)N_DST0 * HID];
__device__ __align__(128) float g_acc1[(size_t)N_DST1 * HID];
__device__ __align__(128) float g_mlp[(size_t)N_DST1 * HID];
__device__ int      g_cnt[T_REL * N_DST0];
__device__ int      g_offs[T_REL * (N_DST0 + 1)];
__device__ int      g_cur[T_REL * N_DST0];
__device__ int      g_eperm[T_REL * E0];
__device__ unsigned g_menc[(size_t)T_REL * N_DST0 * 4];
__device__ double   g_colsum[HID];
__device__ double   g_colsq[HID];
__device__ float    g_mean[HID];
__device__ float    g_rstd[HID];
// bf16 split buffers
__device__ __align__(128) bf16 g_xhi[(size_t)N_SRC0 * IN_DIM];
__device__ __align__(128) bf16 g_xlo[(size_t)N_SRC0 * IN_DIM];
__device__ __align__(128) bf16 g_shi[(size_t)N_DST0 * HID];   // h0 hi  / mlp-relu hi
__device__ __align__(128) bf16 g_slo[(size_t)N_DST0 * HID];
__device__ __align__(128) bf16 g_thi[(size_t)N_DST1 * HID];   // h1 hi
__device__ __align__(128) bf16 g_tlo[(size_t)N_DST1 * HID];
// transposed split weights, packed [N][K]
#define W0T_OFF   0
#define WS0T_OFF  163840
#define W1T_OFF   196608
#define WS1T_OFF  278528
#define WM1T_OFF  294912
#define WM2T_OFF  311296
#define WT_TOTAL  330880
__device__ __align__(128) bf16 g_wthi[WT_TOTAL];
__device__ __align__(128) bf16 g_wtlo[WT_TOTAL];

// ---------------- helpers ----------------
__device__ __forceinline__ unsigned enc_f(float f) {
    unsigned u = __float_as_uint(f);
    return (u & 0x80000000u) ? ~u : (u | 0x80000000u);
}
__device__ __forceinline__ float dec_f(unsigned e) {
    return (e & 0x80000000u) ? __uint_as_float(e ^ 0x80000000u)
                             : __uint_as_float(~e);
}
#define ENC_NEG_INF 0x007FFFFFu

__device__ __forceinline__ void cp_async16(uint32_t dst, const void* src, int sz) {
    asm volatile("cp.async.cg.shared.global [%0], [%1], 16, %2;\n"
                 :: "r"(dst), "l"(src), "r"(sz));
}
__device__ __forceinline__ void cp_commit() {
    asm volatile("cp.async.commit_group;\n");
}
__device__ __forceinline__ void ldsm4(uint32_t* r, uint32_t addr) {
    asm volatile("ldmatrix.sync.aligned.m8n8.x4.shared.b16 {%0,%1,%2,%3}, [%4];"
        : "=r"(r[0]), "=r"(r[1]), "=r"(r[2]), "=r"(r[3]) : "r"(addr));
}
__device__ __forceinline__ void mma16816(float* c, const uint32_t* a, uint32_t b0, uint32_t b1) {
    asm volatile("mma.sync.aligned.m16n8k16.row.col.f32.bf16.bf16.f32 "
        "{%0,%1,%2,%3}, {%4,%5,%6,%7}, {%8,%9}, {%0,%1,%2,%3};"
        : "+f"(c[0]), "+f"(c[1]), "+f"(c[2]), "+f"(c[3])
        : "r"(a[0]), "r"(a[1]), "r"(a[2]), "r"(a[3]), "r"(b0), "r"(b1));
}

// ---------------- split x ----------------
__global__ void split_kernel(const float* __restrict__ X, bf16* __restrict__ hi,
                             bf16* __restrict__ lo, size_t n)
{
    size_t i = (size_t)blockIdx.x * blockDim.x + threadIdx.x;
    if (i >= n) return;
    float v = X[i];
    bf16 h = __float2bfloat16(v);
    hi[i] = h;
    lo[i] = __float2bfloat16(v - __bfloat162float(h));
}

// ---------------- all-weight transpose + split, one launch ----------------
__global__ void splitw_all_kernel(
    const float* __restrict__ W0, const float* __restrict__ Ws0,
    const float* __restrict__ W1, const float* __restrict__ Ws1,
    const float* __restrict__ Wm1, const float* __restrict__ Wm2,
    bf16* __restrict__ hiT, bf16* __restrict__ loT)
{
    int seg = blockIdx.y;
    const float* W; int K, N, nrel, off;
    switch (seg) {
        case 0:  W = W0;  K = IN_DIM; N = HID;     nrel = T_REL; off = W0T_OFF;  break;
        case 1:  W = Ws0; K = IN_DIM; N = HID;     nrel = 1;     off = WS0T_OFF; break;
        case 2:  W = W1;  K = HID;    N = HID;     nrel = T_REL; off = W1T_OFF;  break;
        case 3:  W = Ws1; K = HID;    N = HID;     nrel = 1;     off = WS1T_OFF; break;
        case 4:  W = Wm1; K = HID;    N = HID;     nrel = 1;     off = WM1T_OFF; break;
        default: W = Wm2; K = HID;    N = OUT_DIM; nrel = 1;     off = WM2T_OFF; break;
    }
    int total = nrel * N * K;
    int idx = blockIdx.x * blockDim.x + threadIdx.x;
    if (idx >= total) return;
    int j = idx / (N * K);
    int rem = idx - j * (N * K);
    int n = rem / K, k = rem - n * K;
    float v = W[((size_t)j * K + k) * N + n];
    bf16 h = __float2bfloat16(v);
    hiT[off + idx] = h;
    loT[off + idx] = __float2bfloat16(v - __bfloat162float(h));
}

// ---------------- fused bf16x3 MMA GEMM (+ optional attn-logit epilogue) ------
// A split hi/lo [M][K]; W transposed split [N][K].
// Per k-chunk loads Ahi/Alo/Bhi/Blo, accumulates hi*hi + lo*hi + hi*lo.
// REL: blockIdx.y = relation j. EPI: write el[M][4] (al) and er[n_er][4] (ar).
#define GSTRIDE  40
#define SM_TILE  (128 * GSTRIDE)          // elements
#define SM_AHI   0
#define SM_ALO   SM_TILE
#define SM_BHI   (2 * SM_TILE)
#define SM_BLO   (3 * SM_TILE)
#define SM_STAGE (4 * SM_TILE)            // 20480 elements = 40960 B
#define SMEM_BYTES (2 * SM_STAGE * 2)     // 81920 B

template<bool REL, bool HASBIAS, bool EPI>
__global__ void __launch_bounds__(256, 2) mma_gemm2(
    const bf16* __restrict__ Ahi, const bf16* __restrict__ Alo,
    const bf16* __restrict__ BThi, const bf16* __restrict__ BTlo,
    const float* __restrict__ bias, float* __restrict__ C,
    const float* __restrict__ al, const float* __restrict__ ar,
    float* __restrict__ el, float* __restrict__ er,
    int M, int N, int K, int n_er)
{
    extern __shared__ bf16 sm[];

    int bm0 = blockIdx.x * 128;
    int bn0, ldc;
    if (REL) {
        int j = blockIdx.y;
        BThi += (size_t)j * 128 * K;
        BTlo += (size_t)j * 128 * K;
        C    += (size_t)j * M * 128;
        if (EPI) {
            al += (size_t)j * HID;  ar += (size_t)j * HID;
            el += (size_t)j * M * 4; er += (size_t)j * n_er * 4;
        }
        bn0 = 0; ldc = 128; N = 128;
    } else { bn0 = blockIdx.y * 128; ldc = N; }

    int tid = threadIdx.x, lane = tid & 31, warp = tid >> 5;
    int wm = (warp & 3) * 32, wn = (warp >> 2) * 64;

    int kc = K >> 5;

    int ldrow = tid >> 2;            // 0..63
    int ldcol = (tid & 3) << 3;      // 0,8,16,24 (elements)

    uint32_t s0 = (uint32_t)__cvta_generic_to_shared(sm);

    int mrowA = lane & 15, mcolA = (lane >> 4) << 3;
    int mrowB = (lane & 7) | ((lane >> 4) << 3);
    int mcolB = ((lane >> 3) & 1) << 3;

    float acc[2][8][4];
#pragma unroll
    for (int a = 0; a < 2; a++)
#pragma unroll
        for (int b = 0; b < 8; b++)
#pragma unroll
            for (int c = 0; c < 4; c++) acc[a][b][c] = 0.f;

#define LOAD_STAGE(IT, ST) do {                                                  \
    int kk_ = (IT) << 5;                                                         \
    uint32_t sb_ = s0 + (uint32_t)(ST) * (SM_STAGE * 2);                         \
    _Pragma("unroll")                                                            \
    for (int hh = 0; hh < 2; hh++) {                                             \
        int row = ldrow + hh * 64;                                               \
        int gm = bm0 + row;                                                      \
        int ok = gm < M;                                                         \
        size_t aoff = (size_t)(ok ? gm : 0) * K + kk_ + ldcol;                   \
        cp_async16(sb_ + (SM_AHI + row * GSTRIDE + ldcol) * 2, Ahi + aoff, ok ? 16 : 0); \
        cp_async16(sb_ + (SM_ALO + row * GSTRIDE + ldcol) * 2, Alo + aoff, ok ? 16 : 0); \
        int gn = bn0 + row;                                                      \
        int okb = gn < N;                                                        \
        size_t boff = (size_t)(okb ? gn : 0) * K + kk_ + ldcol;                  \
        cp_async16(sb_ + (SM_BHI + row * GSTRIDE + ldcol) * 2, BThi + boff, okb ? 16 : 0); \
        cp_async16(sb_ + (SM_BLO + row * GSTRIDE + ldcol) * 2, BTlo + boff, okb ? 16 : 0); \
    }                                                                            \
    cp_commit();                                                                 \
} while (0)

    LOAD_STAGE(0, 0);

    for (int it = 0; it < kc; it++) {
        int st = it & 1;
        if (it + 1 < kc) {
            LOAD_STAGE(it + 1, st ^ 1);
            asm volatile("cp.async.wait_group 1;\n" ::: "memory");
        } else {
            asm volatile("cp.async.wait_group 0;\n" ::: "memory");
        }
        __syncthreads();

        uint32_t base = s0 + (uint32_t)st * (SM_STAGE * 2);
#pragma unroll
        for (int s = 0; s < 2; s++) {
            uint32_t ahi[2][4], alo2[2][4];
#pragma unroll
            for (int mt = 0; mt < 2; mt++) {
                uint32_t ra = (wm + mt * 16 + mrowA) * GSTRIDE + s * 16 + mcolA;
                ldsm4(ahi[mt],  base + (SM_AHI + ra) * 2);
                ldsm4(alo2[mt], base + (SM_ALO + ra) * 2);
            }
#pragma unroll
            for (int np = 0; np < 4; np++) {
                uint32_t bh[4];
                ldsm4(bh, base + (SM_BHI + (wn + np * 16 + mrowB) * GSTRIDE + s * 16 + mcolB) * 2);
#pragma unroll
                for (int mt = 0; mt < 2; mt++) {
                    mma16816(acc[mt][2 * np],     ahi[mt],  bh[0], bh[1]);
                    mma16816(acc[mt][2 * np + 1], ahi[mt],  bh[2], bh[3]);
                    mma16816(acc[mt][2 * np],     alo2[mt], bh[0], bh[1]);
                    mma16816(acc[mt][2 * np + 1], alo2[mt], bh[2], bh[3]);
                }
            }
#pragma unroll
            for (int np = 0; np < 4; np++) {
                uint32_t bl[4];
                ldsm4(bl, base + (SM_BLO + (wn + np * 16 + mrowB) * GSTRIDE + s * 16 + mcolB) * 2);
#pragma unroll
                for (int mt = 0; mt < 2; mt++) {
                    mma16816(acc[mt][2 * np],     ahi[mt], bl[0], bl[1]);
                    mma16816(acc[mt][2 * np + 1], ahi[mt], bl[2], bl[3]);
                }
            }
        }
        __syncthreads();
    }
#undef LOAD_STAGE

    int trow = lane >> 2, tcol = (lane & 3) << 1;
#pragma unroll
    for (int mt = 0; mt < 2; mt++) {
        int gm0 = bm0 + wm + mt * 16 + trow;
        int gm1 = gm0 + 8;
        // C writes
#pragma unroll
        for (int nt = 0; nt < 8; nt++) {
            int gn = bn0 + wn + nt * 8 + tcol;
            bool okn0 = REL || (gn < N);
            bool okn1 = REL || (gn + 1 < N);
            float b0a = 0.f, b1a = 0.f;
            if (HASBIAS) {
                if (okn0) b0a = bias[gn];
                if (okn1) b1a = bias[gn + 1];
            }
            float* cr = acc[mt][nt];
            if (gm0 < M) {
                if (okn0) C[(size_t)gm0 * ldc + gn]     = cr[0] + b0a;
                if (okn1) C[(size_t)gm0 * ldc + gn + 1] = cr[1] + b1a;
            }
            if (gm1 < M) {
                if (okn0) C[(size_t)gm1 * ldc + gn]     = cr[2] + b0a;
                if (okn1) C[(size_t)gm1 * ldc + gn + 1] = cr[3] + b1a;
            }
        }
        if (EPI) {
            // el/er: per warp, cols [wn,wn+64) = heads h0=wn/32, h0+1
            float eA0 = 0.f, eB0 = 0.f, rA0 = 0.f, rB0 = 0.f;
            float eA1 = 0.f, eB1 = 0.f, rA1 = 0.f, rB1 = 0.f;
#pragma unroll
            for (int nt = 0; nt < 8; nt++) {
                int gn = wn + nt * 8 + tcol;
                float a0v = al[gn], a1v = al[gn + 1];
                float r0v = ar[gn], r1v = ar[gn + 1];
                float* cr = acc[mt][nt];
                float c0 = cr[0] * a0v + cr[1] * a1v;
                float c1 = cr[2] * a0v + cr[3] * a1v;
                float d0 = cr[0] * r0v + cr[1] * r1v;
                float d1 = cr[2] * r0v + cr[3] * r1v;
                if (nt < 4) { eA0 += c0; eA1 += c1; rA0 += d0; rA1 += d1; }
                else        { eB0 += c0; eB1 += c1; rB0 += d0; rB1 += d1; }
            }
#pragma unroll
            for (int d = 1; d < 4; d <<= 1) {
                eA0 += __shfl_xor_sync(0xffffffffu, eA0, d);
                eB0 += __shfl_xor_sync(0xffffffffu, eB0, d);
                rA0 += __shfl_xor_sync(0xffffffffu, rA0, d);
                rB0 += __shfl_xor_sync(0xffffffffu, rB0, d);
                eA1 += __shfl_xor_sync(0xffffffffu, eA1, d);
                eB1 += __shfl_xor_sync(0xffffffffu, eB1, d);
                rA1 += __shfl_xor_sync(0xffffffffu, rA1, d);
                rB1 += __shfl_xor_sync(0xffffffffu, rB1, d);
            }
            if ((lane & 3) == 0) {
                int h0 = wn >> 5;  // 0 or 2
                if (gm0 < M) {
                    el[(size_t)gm0 * 4 + h0]     = eA0;
                    el[(size_t)gm0 * 4 + h0 + 1] = eB0;
                    if (gm0 < n_er) {
                        er[(size_t)gm0 * 4 + h0]     = rA0;
                        er[(size_t)gm0 * 4 + h0 + 1] = rB0;
                    }
                }
                if (gm1 < M) {
                    el[(size_t)gm1 * 4 + h0]     = eA1;
                    el[(size_t)gm1 * 4 + h0 + 1] = eB1;
                    if (gm1 < n_er) {
                        er[(size_t)gm1 * 4 + h0]     = rA1;
                        er[(size_t)gm1 * 4 + h0 + 1] = rB1;
                    }
                }
            }
        }
    }
}

// ---------------- CSR build (batched over relations) ----------------
__global__ void fill_int_kernel(int* p, int n, int v) {
    int i = blockIdx.x * blockDim.x + threadIdx.x;
    if (i < n) p[i] = v;
}
__global__ void fill_uint_kernel(unsigned* p, int n, unsigned v) {
    int i = blockIdx.x * blockDim.x + threadIdx.x;
    if (i < n) p[i] = v;
}
__global__ void hist_kernel(const int* __restrict__ dstAll, int E, int* __restrict__ cnt) {
    int j = blockIdx.y;
    int e = blockIdx.x * blockDim.x + threadIdx.x;
    if (e < E) atomicAdd(&cnt[j * N_DST0 + dstAll[(size_t)j * E + e]], 1);
}
__global__ void scan_kernel(const int* __restrict__ cntAll, int* __restrict__ offsAll, int n) {
    const int* cnt = cntAll + blockIdx.x * N_DST0;
    int* offs = offsAll + blockIdx.x * (N_DST0 + 1);
    __shared__ int wsum[32];
    __shared__ int running_s;
    if (threadIdx.x == 0) running_s = 0;
    __syncthreads();
    int lane = threadIdx.x & 31, wid = threadIdx.x >> 5;
    for (int base = 0; base < n; base += 1024) {
        int i = base + (int)threadIdx.x;
        int v = (i < n) ? cnt[i] : 0;
        int x = v;
#pragma unroll
        for (int d = 1; d < 32; d <<= 1) {
            int t = __shfl_up_sync(0xffffffffu, x, d);
            if (lane >= d) x += t;
        }
        if (lane == 31) wsum[wid] = x;
        __syncthreads();
        if (wid == 0) {
            int y = wsum[lane];
#pragma unroll
            for (int d = 1; d < 32; d <<= 1) {
                int t = __shfl_up_sync(0xffffffffu, y, d);
                if (lane >= d) y += t;
            }
            wsum[lane] = y;
        }
        __syncthreads();
        int incl = x + (wid ? wsum[wid - 1] : 0);
        int r = running_s;
        if (i < n) offs[i] = r + (incl - v);
        int total = wsum[31];
        __syncthreads();
        if (threadIdx.x == 0) running_s = r + total;
        __syncthreads();
    }
    if (threadIdx.x == 0) offs[n] = running_s;
}
__global__ void copy_off_kernel(const int* __restrict__ offs, int* __restrict__ cur, int n) {
    int j = blockIdx.y;
    int i = blockIdx.x * blockDim.x + threadIdx.x;
    if (i < n) cur[j * N_DST0 + i] = offs[j * (N_DST0 + 1) + i];
}
__global__ void scatter_kernel(const int* __restrict__ dstAll, int E,
                               int* __restrict__ cur, int* __restrict__ eperm) {
    int j = blockIdx.y;
    int e = blockIdx.x * blockDim.x + threadIdx.x;
    if (e < E) {
        int pos = atomicAdd(&cur[j * N_DST0 + dstAll[(size_t)j * E + e]], 1);
        eperm[(size_t)j * E0 + pos] = e;
    }
}
__global__ void edge_max_kernel(const int* __restrict__ srcAll, const int* __restrict__ dstAll,
                                const float* __restrict__ el, const float* __restrict__ er,
                                unsigned* __restrict__ menc, int E, int n_src, int n_dst)
{
    int j = blockIdx.y;
    int e = blockIdx.x * blockDim.x + threadIdx.x;
    if (e >= E) return;
    int s = srcAll[(size_t)j * E + e], d = dstAll[(size_t)j * E + e];
    float4 L = *(const float4*)(el + ((size_t)j * n_src + s) * 4);
    float4 R = *(const float4*)(er + ((size_t)j * n_dst + d) * 4);
    float lv[4] = {L.x, L.y, L.z, L.w};
    float rv[4] = {R.x, R.y, R.z, R.w};
    unsigned* mj = menc + (size_t)j * N_DST0 * 4;
#pragma unroll
    for (int h = 0; h < 4; h++) {
        float v = lv[h] + rv[h];
        v = v > 0.f ? v : NEG_SLOPE * v;
        atomicMax(&mj[(size_t)d * 4 + h], enc_f(v));
    }
}

// ---------------- aggregation: one block per dst node, all relations ----------------
__global__ void aggregate_all_kernel(
    const float* __restrict__ Hs, int hsrows,
    const float* __restrict__ el, const float* __restrict__ er,
    const unsigned* __restrict__ menc,
    const int* __restrict__ offs, const int* __restrict__ eperm,
    const int* __restrict__ srcAll, int E,
    const float* __restrict__ b, int n_dst, float* __restrict__ out)
{
    int nd = blockIdx.x;
    int t = threadIdx.x;
    int h = t >> 5;
    __shared__ int   s_src[128];
    __shared__ float s_w[4][128];
    float total = 0.f;

    for (int j = 0; j < T_REL; j++) {
        const float* Hj  = Hs + (size_t)j * hsrows * HID;
        const float* elj = el + (size_t)j * hsrows * 4;
        const float* erj = er + (size_t)j * n_dst * 4;
        const unsigned* mj = menc + (size_t)j * N_DST0 * 4;
        const int* offj = offs + j * (N_DST0 + 1);
        const int* epj  = eperm + (size_t)j * E0;
        const int* sj   = srcAll + (size_t)j * E;

        total += b[j * HID + t];
        int o0 = offj[nd], o1 = offj[nd + 1];
        int cnt = o1 - o0;
        if (cnt == 0) continue;

        float m_all[4], er_all[4];
        {
            float4 e4 = *(const float4*)(erj + (size_t)nd * 4);
            er_all[0] = e4.x; er_all[1] = e4.y; er_all[2] = e4.z; er_all[3] = e4.w;
            uint4 m4 = *(const uint4*)(mj + (size_t)nd * 4);
            m_all[0] = dec_f(m4.x); m_all[1] = dec_f(m4.y);
            m_all[2] = dec_f(m4.z); m_all[3] = dec_f(m4.w);
        }
        float acc = 0.f, ssum = 0.f;
        for (int c0 = 0; c0 < cnt; c0 += 128) {
            int k = c0 + t;
            if (k < cnt) {
                int e = epj[o0 + k];
                int s = sj[e];
                s_src[t] = s;
                float4 L = *(const float4*)(elj + (size_t)s * 4);
                float lv[4] = {L.x, L.y, L.z, L.w};
#pragma unroll
                for (int hh = 0; hh < 4; hh++) {
                    float v = lv[hh] + er_all[hh];
                    v = v > 0.f ? v : NEG_SLOPE * v;
                    s_w[hh][t] = __expf(v - m_all[hh]);
                }
            }
            __syncthreads();
            int len = min(128, cnt - c0);
            const float* wrow = s_w[h];
#pragma unroll 4
            for (int k2 = 0; k2 < len; k2++) {
                float w = wrow[k2];
                float x = Hj[(size_t)s_src[k2] * HID + t];
                acc += w * x;
                ssum += w;
            }
            __syncthreads();
        }
        total += acc / ssum;
    }
    out[(size_t)nd * HID + t] += total;
}

// ---------------- column norm + activation (+ bf16 split output) ----------------
__global__ void colstat_zero_kernel() {
    int t = threadIdx.x;
    g_colsum[t] = 0.0; g_colsq[t] = 0.0;
}
__global__ void colstat_partial_kernel(const float* __restrict__ X, int nrows) {
    int t = threadIdx.x;
    int r0 = blockIdx.x * 256;
    int r1 = min(r0 + 256, nrows);
    float fs = 0.f, fq = 0.f;
    for (int r = r0; r < r1; r++) {
        float v = X[(size_t)r * HID + t];
        fs += v; fq += v * v;
    }
    atomicAdd(&g_colsum[t], (double)fs);
    atomicAdd(&g_colsq[t], (double)fq);
}
__global__ void colstat_final_kernel(int nrows) {
    int t = threadIdx.x;
    double inv = 1.0 / (double)nrows;
    double mean = g_colsum[t] * inv;
    double var = g_colsq[t] * inv - mean * mean;
    g_mean[t] = (float)mean;
    g_rstd[t] = (float)(1.0 / sqrt(var + (double)EPS_LN));
}
// act: 0 = elu, 1 = relu; writes bf16 hi/lo split directly
__global__ void norm_act_split_kernel(const float* __restrict__ X,
                                      const float* __restrict__ g,
                                      const float* __restrict__ be,
                                      bf16* __restrict__ hi, bf16* __restrict__ lo,
                                      int nrows, int act)
{
    int idx = blockIdx.x * blockDim.x + threadIdx.x;
    if (idx >= nrows * HID) return;
    int t = idx & (HID - 1);
    float v = (X[idx] - g_mean[t]) * g_rstd[t] * g[t] + be[t];
    if (act) v = v > 0.f ? v : 0.f;
    else     v = v > 0.f ? v : expm1f(v);
    bf16 h = __float2bfloat16(v);
    hi[idx] = h;
    lo[idx] = __float2bfloat16(v - __bfloat162float(h));
}

// ---------------- host orchestration ----------------
static inline void* sym(const void* s) { void* p = nullptr; cudaGetSymbolAddress(&p, s); return p; }

static void set_smem_attrs() {
    cudaFuncSetAttribute(mma_gemm2<true,  false, true >, cudaFuncAttributeMaxDynamicSharedMemorySize, SMEM_BYTES);
    cudaFuncSetAttribute(mma_gemm2<false, true,  false>, cudaFuncAttributeMaxDynamicSharedMemorySize, SMEM_BYTES);
}

static void run_layer(const bf16* Ahi, const bf16* Alo, int n_src, int n_dst, int Kdim,
                      const bf16* WtHi, const bf16* WtLo,
                      const bf16* WsHi, const bf16* WsLo,
                      const float* alpha_l, const float* alpha_r,
                      const float* b, const float* bs,
                      const float* gamma, const float* beta,
                      const int* srcAll, const int* dstAll, int E,
                      float* Hs, float* elbuf, float* erbuf,
                      float* accbuf, bf16* outhi, bf16* outlo)
{
    int* cnt = (int*)sym(g_cnt);
    int* offs = (int*)sym(g_offs);
    int* cur = (int*)sym(g_cur);
    int* eperm = (int*)sym(g_eperm);
    unsigned* menc = (unsigned*)sym(g_menc);

    // CSR build prefix (before GEMM so the REL GEMM lands at launch index 5)
    fill_int_kernel<<<(T_REL * N_DST0 + 255) / 256, 256>>>(cnt, T_REL * N_DST0, 0);
    { dim3 grid((E + 255) / 256, T_REL);
      hist_kernel<<<grid, 256>>>(dstAll, E, cnt); }
    scan_kernel<<<T_REL, 1024>>>(cnt, offs, n_dst);

    {   // Hs = A @ W[j] for all relations, with el/er epilogue
        dim3 grid((n_src + 127) / 128, T_REL);
        mma_gemm2<true, false, true><<<grid, 256, SMEM_BYTES>>>(
            Ahi, Alo, WtHi, WtLo, nullptr, Hs,
            alpha_l, alpha_r, elbuf, erbuf, n_src, HID, Kdim, n_dst);
    }

    { dim3 grid((n_dst + 255) / 256, T_REL);
      copy_off_kernel<<<grid, 256>>>(offs, cur, n_dst); }
    { dim3 grid((E + 255) / 256, T_REL);
      scatter_kernel<<<grid, 256>>>(dstAll, E, cur, eperm); }
    fill_uint_kernel<<<(T_REL * N_DST0 * 4 + 255) / 256, 256>>>(menc, T_REL * N_DST0 * 4, ENC_NEG_INF);

    {   // acc = A[:n_dst] @ Ws + bs
        dim3 grid((n_dst + 127) / 128, 1);
        mma_gemm2<false, true, false><<<grid, 256, SMEM_BYTES>>>(
            Ahi, Alo, WsHi, WsLo, bs, accbuf,
            nullptr, nullptr, nullptr, nullptr, n_dst, HID, Kdim, 0);
    }

    { dim3 grid((E + 255) / 256, T_REL);
      edge_max_kernel<<<grid, 256>>>(srcAll, dstAll, elbuf, erbuf, menc, E, n_src, n_dst); }

    aggregate_all_kernel<<<n_dst, 128>>>(Hs, n_src, elbuf, erbuf, menc, offs, eperm,
                                         srcAll, E, b, n_dst, accbuf);

    colstat_zero_kernel<<<1, 128>>>();
    colstat_partial_kernel<<<(n_dst + 255) / 256, 128>>>(accbuf, n_dst);
    colstat_final_kernel<<<1, 128>>>(n_dst);
    norm_act_split_kernel<<<(n_dst * HID + 255) / 256, 256>>>(accbuf, gamma, beta,
                                                              outhi, outlo, n_dst, 0);
}

extern "C" void kernel_launch(void* const* d_in, const int* in_sizes, int n_in,
                              void* d_out, int out_size)
{
    (void)in_sizes; (void)n_in; (void)out_size;
    const float* x   = (const float*)d_in[0];
    const float* W0  = (const float*)d_in[1];
    const float* al0 = (const float*)d_in[2];
    const float* ar0 = (const float*)d_in[3];
    const float* b0  = (const float*)d_in[4];
    const float* Ws0 = (const float*)d_in[5];
    const float* bs0 = (const float*)d_in[6];
    const float* g0  = (const float*)d_in[7];
    const float* be0 = (const float*)d_in[8];
    const float* W1  = (const float*)d_in[9];
    const float* al1 = (const float*)d_in[10];
    const float* ar1 = (const float*)d_in[11];
    const float* b1  = (const float*)d_in[12];
    const float* Ws1 = (const float*)d_in[13];
    const float* bs1 = (const float*)d_in[14];
    const float* g1  = (const float*)d_in[15];
    const float* be1 = (const float*)d_in[16];
    const float* Wm1 = (const float*)d_in[17];
    const float* bm1 = (const float*)d_in[18];
    const float* gm  = (const float*)d_in[19];
    const float* bem = (const float*)d_in[20];
    const float* Wm2 = (const float*)d_in[21];
    const float* bm2 = (const float*)d_in[22];
    const int* src0  = (const int*)d_in[23];
    const int* dst0  = (const int*)d_in[24];
    const int* src1  = (const int*)d_in[25];
    const int* dst1  = (const int*)d_in[26];
    float* out = (float*)d_out;

    float* Hs0  = (float*)sym(g_Hs0);
    float* Hs1  = (float*)sym(g_Hs1);
    float* el0p = (float*)sym(g_el0);
    float* er0p = (float*)sym(g_er0);
    float* el1p = (float*)sym(g_el1);
    float* er1p = (float*)sym(g_er1);
    float* acc0 = (float*)sym(g_acc0);
    float* acc1 = (float*)sym(g_acc1);
    float* mlp  = (float*)sym(g_mlp);
    bf16* xhi = (bf16*)sym(g_xhi);
    bf16* xlo = (bf16*)sym(g_xlo);
    bf16* shi = (bf16*)sym(g_shi);
    bf16* slo = (bf16*)sym(g_slo);
    bf16* thi = (bf16*)sym(g_thi);
    bf16* tlo = (bf16*)sym(g_tlo);
    bf16* wthi = (bf16*)sym(g_wthi);
    bf16* wtlo = (bf16*)sym(g_wtlo);

    set_smem_attrs();

    // launch 0: all weight transpose+split
    {
        dim3 g((T_REL * HID * IN_DIM + 255) / 256, 6);
        splitw_all_kernel<<<g, 256>>>(W0, Ws0, W1, Ws1, Wm1, Wm2, wthi, wtlo);
    }
    // launch 1: split x
    {
        size_t n = (size_t)N_SRC0 * IN_DIM;
        split_kernel<<<(unsigned)((n + 255) / 256), 256>>>(x, xhi, xlo, n);
    }

    // Layer 0 (launch 5 = REL GEMM, profiled by ncu -s 5 -c 1)
    run_layer(xhi, xlo, N_SRC0, N_DST0, IN_DIM,
              wthi + W0T_OFF, wtlo + W0T_OFF, wthi + WS0T_OFF, wtlo + WS0T_OFF,
              al0, ar0, b0, bs0, g0, be0,
              src0, dst0, E0, Hs0, el0p, er0p, acc0, shi, slo);

    // Layer 1
    run_layer(shi, slo, N_DST0, N_DST1, HID,
              wthi + W1T_OFF, wtlo + W1T_OFF, wthi + WS1T_OFF, wtlo + WS1T_OFF,
              al1, ar1, b1, bs1, g1, be1,
              src1, dst1, E1, Hs1, el1p, er1p, acc1, thi, tlo);

    // MLP
    {
        dim3 grid((N_DST1 + 127) / 128, 1);
        mma_gemm2<false, true, false><<<grid, 256, SMEM_BYTES>>>(
            thi, tlo, wthi + WM1T_OFF, wtlo + WM1T_OFF, bm1, mlp,
            nullptr, nullptr, nullptr, nullptr, N_DST1, HID, HID, 0);
    }
    colstat_zero_kernel<<<1, 128>>>();
    colstat_partial_kernel<<<(N_DST1 + 255) / 256, 128>>>(mlp, N_DST1);
    colstat_final_kernel<<<1, 128>>>(N_DST1);
    norm_act_split_kernel<<<(N_DST1 * HID + 255) / 256, 256>>>(mlp, gm, bem, shi, slo, N_DST1, 1);
    {
        dim3 grid((N_DST1 + 127) / 128, (OUT_DIM + 127) / 128);
        mma_gemm2<false, true, false><<<grid, 256, SMEM_BYTES>>>(
            shi, slo, wthi + WM2T_OFF, wtlo + WM2T_OFF, bm2, out,
            nullptr, nullptr, nullptr, nullptr, N_DST1, OUT_DIM, HID, 0);
    }
}

// round 5
// speedup vs baseline: 1.5247x; 1.0073x over previous
#include <cuda_runtime.h>
#include <cuda_bf16.h>
#include <cuda_fp16.h>
#include <cstdint>

#define N_SRC0 120000
#define N_DST0 40000
#define N_DST1 10000
#define T_REL  5
#define HID    128
#define IN_DIM 256
#define OUT_DIM 153
#define E0 800000
#define E1 300000
#define NEG_SLOPE 0.2f
#define EPS_LN 1e-5f

typedef __nv_bfloat16 bf16;

// ---------------- static device scratch ----------------
__device__ __align__(128) __half g_Hs0[(size_t)T_REL * N_SRC0 * HID];
__device__ __align__(128) __half g_Hs1[(size_t)T_REL * N_DST0 * HID];
__device__ __align__(16)  float g_el0[(size_t)T_REL * N_SRC0 * 4];
__device__ __align__(16)  float g_er0[(size_t)T_REL * N_DST0 * 4];
__device__ __align__(16)  float g_el1[(size_t)T_REL * N_DST0 * 4];
__device__ __align__(16)  float g_er1[(size_t)T_REL * N_DST1 * 4];
__device__ __align__(128) float g_acc0[(size_t)N_DST0 * HID];
__device__ __align__(128) float g_acc1[(size_t)N_DST1 * HID];
__device__ __align__(128) float g_mlp[(size_t)N_DST1 * HID];
__device__ int      g_cnt[T_REL * N_DST0];
__device__ int      g_offs[T_REL * (N_DST0 + 1)];
__device__ int      g_cur[T_REL * N_DST0];
__device__ int      g_eperm[T_REL * E0];
__device__ unsigned g_menc[(size_t)T_REL * N_DST0 * 4];
__device__ double   g_colsum[HID];
__device__ double   g_colsq[HID];
__device__ float    g_mean[HID];
__device__ float    g_rstd[HID];
// bf16 split buffers
__device__ __align__(128) bf16 g_xhi[(size_t)N_SRC0 * IN_DIM];
__device__ __align__(128) bf16 g_xlo[(size_t)N_SRC0 * IN_DIM];
__device__ __align__(128) bf16 g_shi[(size_t)N_DST0 * HID];
__device__ __align__(128) bf16 g_slo[(size_t)N_DST0 * HID];
__device__ __align__(128) bf16 g_thi[(size_t)N_DST1 * HID];
__device__ __align__(128) bf16 g_tlo[(size_t)N_DST1 * HID];
// transposed split weights, packed [N][K]
#define W0T_OFF   0
#define WS0T_OFF  163840
#define W1T_OFF   196608
#define WS1T_OFF  278528
#define WM1T_OFF  294912
#define WM2T_OFF  311296
#define WT_TOTAL  330880
__device__ __align__(128) bf16 g_wthi[WT_TOTAL];
__device__ __align__(128) bf16 g_wtlo[WT_TOTAL];

// ---------------- helpers ----------------
__device__ __forceinline__ unsigned enc_f(float f) {
    unsigned u = __float_as_uint(f);
    return (u & 0x80000000u) ? ~u : (u | 0x80000000u);
}
__device__ __forceinline__ float dec_f(unsigned e) {
    return (e & 0x80000000u) ? __uint_as_float(e ^ 0x80000000u)
                             : __uint_as_float(~e);
}
#define ENC_NEG_INF 0x007FFFFFu

__device__ __forceinline__ void cp_async16(uint32_t dst, const void* src, int sz) {
    asm volatile("cp.async.cg.shared.global [%0], [%1], 16, %2;\n"
                 :: "r"(dst), "l"(src), "r"(sz));
}
__device__ __forceinline__ void cp_commit() {
    asm volatile("cp.async.commit_group;\n");
}
__device__ __forceinline__ void ldsm4(uint32_t* r, uint32_t addr) {
    asm volatile("ldmatrix.sync.aligned.m8n8.x4.shared.b16 {%0,%1,%2,%3}, [%4];"
        : "=r"(r[0]), "=r"(r[1]), "=r"(r[2]), "=r"(r[3]) : "r"(addr));
}
__device__ __forceinline__ void mma16816(float* c, const uint32_t* a, uint32_t b0, uint32_t b1) {
    asm volatile("mma.sync.aligned.m16n8k16.row.col.f32.bf16.bf16.f32 "
        "{%0,%1,%2,%3}, {%4,%5,%6,%7}, {%8,%9}, {%0,%1,%2,%3};"
        : "+f"(c[0]), "+f"(c[1]), "+f"(c[2]), "+f"(c[3])
        : "r"(a[0]), "r"(a[1]), "r"(a[2]), "r"(a[3]), "r"(b0), "r"(b1));
}

// ---------------- split x ----------------
__global__ void split_kernel(const float* __restrict__ X, bf16* __restrict__ hi,
                             bf16* __restrict__ lo, size_t n)
{
    size_t i = (size_t)blockIdx.x * blockDim.x + threadIdx.x;
    if (i >= n) return;
    float v = X[i];
    bf16 h = __float2bfloat16(v);
    hi[i] = h;
    lo[i] = __float2bfloat16(v - __bfloat162float(h));
}

// ---------------- all-weight transpose + split, one launch ----------------
__global__ void splitw_all_kernel(
    const float* __restrict__ W0, const float* __restrict__ Ws0,
    const float* __restrict__ W1, const float* __restrict__ Ws1,
    const float* __restrict__ Wm1, const float* __restrict__ Wm2,
    bf16* __restrict__ hiT, bf16* __restrict__ loT)
{
    int seg = blockIdx.y;
    const float* W; int K, N, nrel, off;
    switch (seg) {
        case 0:  W = W0;  K = IN_DIM; N = HID;     nrel = T_REL; off = W0T_OFF;  break;
        case 1:  W = Ws0; K = IN_DIM; N = HID;     nrel = 1;     off = WS0T_OFF; break;
        case 2:  W = W1;  K = HID;    N = HID;     nrel = T_REL; off = W1T_OFF;  break;
        case 3:  W = Ws1; K = HID;    N = HID;     nrel = 1;     off = WS1T_OFF; break;
        case 4:  W = Wm1; K = HID;    N = HID;     nrel = 1;     off = WM1T_OFF; break;
        default: W = Wm2; K = HID;    N = OUT_DIM; nrel = 1;     off = WM2T_OFF; break;
    }
    int total = nrel * N * K;
    int idx = blockIdx.x * blockDim.x + threadIdx.x;
    if (idx >= total) return;
    int j = idx / (N * K);
    int rem = idx - j * (N * K);
    int n = rem / K, k = rem - n * K;
    float v = W[((size_t)j * K + k) * N + n];
    bf16 h = __float2bfloat16(v);
    hiT[off + idx] = h;
    loT[off + idx] = __float2bfloat16(v - __bfloat162float(h));
}

// ---------------- fused bf16x3 MMA GEMM (+ optional attn-logit epilogue) ------
// A split hi/lo [M][K]; W transposed split [N][K].
// REL: C is fp16 (Hs), blockIdx.y = relation j, with el/er epilogue.
// !REL: C is fp32 (+bias).
#define GSTRIDE  40
#define SM_TILE  (128 * GSTRIDE)
#define SM_AHI   0
#define SM_ALO   SM_TILE
#define SM_BHI   (2 * SM_TILE)
#define SM_BLO   (3 * SM_TILE)
#define SM_STAGE (4 * SM_TILE)
#define SMEM_BYTES (2 * SM_STAGE * 2)

template<bool REL, bool HASBIAS, bool EPI>
__global__ void __launch_bounds__(256, 2) mma_gemm2(
    const bf16* __restrict__ Ahi, const bf16* __restrict__ Alo,
    const bf16* __restrict__ BThi, const bf16* __restrict__ BTlo,
    const float* __restrict__ bias, void* __restrict__ Cv,
    const float* __restrict__ al, const float* __restrict__ ar,
    float* __restrict__ el, float* __restrict__ er,
    int M, int N, int K, int n_er)
{
    extern __shared__ bf16 sm[];

    __half* Ch = (__half*)Cv;
    float*  Cf = (float*)Cv;

    int bm0 = blockIdx.x * 128;
    int bn0, ldc;
    if (REL) {
        int j = blockIdx.y;
        BThi += (size_t)j * 128 * K;
        BTlo += (size_t)j * 128 * K;
        Ch   += (size_t)j * M * 128;
        if (EPI) {
            al += (size_t)j * HID;  ar += (size_t)j * HID;
            el += (size_t)j * M * 4; er += (size_t)j * n_er * 4;
        }
        bn0 = 0; ldc = 128; N = 128;
    } else { bn0 = blockIdx.y * 128; ldc = N; }

    int tid = threadIdx.x, lane = tid & 31, warp = tid >> 5;
    int wm = (warp & 3) * 32, wn = (warp >> 2) * 64;

    int kc = K >> 5;

    int ldrow = tid >> 2;
    int ldcol = (tid & 3) << 3;

    uint32_t s0 = (uint32_t)__cvta_generic_to_shared(sm);

    int mrowA = lane & 15, mcolA = (lane >> 4) << 3;
    int mrowB = (lane & 7) | ((lane >> 4) << 3);
    int mcolB = ((lane >> 3) & 1) << 3;

    float acc[2][8][4];
#pragma unroll
    for (int a = 0; a < 2; a++)
#pragma unroll
        for (int b = 0; b < 8; b++)
#pragma unroll
            for (int c = 0; c < 4; c++) acc[a][b][c] = 0.f;

#define LOAD_STAGE(IT, ST) do {                                                  \
    int kk_ = (IT) << 5;                                                         \
    uint32_t sb_ = s0 + (uint32_t)(ST) * (SM_STAGE * 2);                         \
    _Pragma("unroll")                                                            \
    for (int hh = 0; hh < 2; hh++) {                                             \
        int row = ldrow + hh * 64;                                               \
        int gm = bm0 + row;                                                      \
        int ok = gm < M;                                                         \
        size_t aoff = (size_t)(ok ? gm : 0) * K + kk_ + ldcol;                   \
        cp_async16(sb_ + (SM_AHI + row * GSTRIDE + ldcol) * 2, Ahi + aoff, ok ? 16 : 0); \
        cp_async16(sb_ + (SM_ALO + row * GSTRIDE + ldcol) * 2, Alo + aoff, ok ? 16 : 0); \
        int gn = bn0 + row;                                                      \
        int okb = gn < N;                                                        \
        size_t boff = (size_t)(okb ? gn : 0) * K + kk_ + ldcol;                  \
        cp_async16(sb_ + (SM_BHI + row * GSTRIDE + ldcol) * 2, BThi + boff, okb ? 16 : 0); \
        cp_async16(sb_ + (SM_BLO + row * GSTRIDE + ldcol) * 2, BTlo + boff, okb ? 16 : 0); \
    }                                                                            \
    cp_commit();                                                                 \
} while (0)

    LOAD_STAGE(0, 0);

    for (int it = 0; it < kc; it++) {
        int st = it & 1;
        if (it + 1 < kc) {
            LOAD_STAGE(it + 1, st ^ 1);
            asm volatile("cp.async.wait_group 1;\n" ::: "memory");
        } else {
            asm volatile("cp.async.wait_group 0;\n" ::: "memory");
        }
        __syncthreads();

        uint32_t base = s0 + (uint32_t)st * (SM_STAGE * 2);
#pragma unroll
        for (int s = 0; s < 2; s++) {
            uint32_t ahi[2][4], alo2[2][4];
#pragma unroll
            for (int mt = 0; mt < 2; mt++) {
                uint32_t ra = (wm + mt * 16 + mrowA) * GSTRIDE + s * 16 + mcolA;
                ldsm4(ahi[mt],  base + (SM_AHI + ra) * 2);
                ldsm4(alo2[mt], base + (SM_ALO + ra) * 2);
            }
#pragma unroll
            for (int np = 0; np < 4; np++) {
                uint32_t bh[4];
                ldsm4(bh, base + (SM_BHI + (wn + np * 16 + mrowB) * GSTRIDE + s * 16 + mcolB) * 2);
#pragma unroll
                for (int mt = 0; mt < 2; mt++) {
                    mma16816(acc[mt][2 * np],     ahi[mt],  bh[0], bh[1]);
                    mma16816(acc[mt][2 * np + 1], ahi[mt],  bh[2], bh[3]);
                    mma16816(acc[mt][2 * np],     alo2[mt], bh[0], bh[1]);
                    mma16816(acc[mt][2 * np + 1], alo2[mt], bh[2], bh[3]);
                }
            }
#pragma unroll
            for (int np = 0; np < 4; np++) {
                uint32_t bl[4];
                ldsm4(bl, base + (SM_BLO + (wn + np * 16 + mrowB) * GSTRIDE + s * 16 + mcolB) * 2);
#pragma unroll
                for (int mt = 0; mt < 2; mt++) {
                    mma16816(acc[mt][2 * np],     ahi[mt], bl[0], bl[1]);
                    mma16816(acc[mt][2 * np + 1], ahi[mt], bl[2], bl[3]);
                }
            }
        }
        __syncthreads();
    }
#undef LOAD_STAGE

    int trow = lane >> 2, tcol = (lane & 3) << 1;
#pragma unroll
    for (int mt = 0; mt < 2; mt++) {
        int gm0 = bm0 + wm + mt * 16 + trow;
        int gm1 = gm0 + 8;
#pragma unroll
        for (int nt = 0; nt < 8; nt++) {
            int gn = bn0 + wn + nt * 8 + tcol;
            float* cr = acc[mt][nt];
            if (REL) {
                if (gm0 < M) {
                    Ch[(size_t)gm0 * ldc + gn]     = __float2half(cr[0]);
                    Ch[(size_t)gm0 * ldc + gn + 1] = __float2half(cr[1]);
                }
                if (gm1 < M) {
                    Ch[(size_t)gm1 * ldc + gn]     = __float2half(cr[2]);
                    Ch[(size_t)gm1 * ldc + gn + 1] = __float2half(cr[3]);
                }
            } else {
                bool okn0 = gn < N, okn1 = gn + 1 < N;
                float b0a = 0.f, b1a = 0.f;
                if (HASBIAS) {
                    if (okn0) b0a = bias[gn];
                    if (okn1) b1a = bias[gn + 1];
                }
                if (gm0 < M) {
                    if (okn0) Cf[(size_t)gm0 * ldc + gn]     = cr[0] + b0a;
                    if (okn1) Cf[(size_t)gm0 * ldc + gn + 1] = cr[1] + b1a;
                }
                if (gm1 < M) {
                    if (okn0) Cf[(size_t)gm1 * ldc + gn]     = cr[2] + b0a;
                    if (okn1) Cf[(size_t)gm1 * ldc + gn + 1] = cr[3] + b1a;
                }
            }
        }
        if (EPI) {
            float eA0 = 0.f, eB0 = 0.f, rA0 = 0.f, rB0 = 0.f;
            float eA1 = 0.f, eB1 = 0.f, rA1 = 0.f, rB1 = 0.f;
#pragma unroll
            for (int nt = 0; nt < 8; nt++) {
                int gn = wn + nt * 8 + tcol;
                float a0v = al[gn], a1v = al[gn + 1];
                float r0v = ar[gn], r1v = ar[gn + 1];
                float* cr = acc[mt][nt];
                float c0 = cr[0] * a0v + cr[1] * a1v;
                float c1 = cr[2] * a0v + cr[3] * a1v;
                float d0 = cr[0] * r0v + cr[1] * r1v;
                float d1 = cr[2] * r0v + cr[3] * r1v;
                if (nt < 4) { eA0 += c0; eA1 += c1; rA0 += d0; rA1 += d1; }
                else        { eB0 += c0; eB1 += c1; rB0 += d0; rB1 += d1; }
            }
#pragma unroll
            for (int d = 1; d < 4; d <<= 1) {
                eA0 += __shfl_xor_sync(0xffffffffu, eA0, d);
                eB0 += __shfl_xor_sync(0xffffffffu, eB0, d);
                rA0 += __shfl_xor_sync(0xffffffffu, rA0, d);
                rB0 += __shfl_xor_sync(0xffffffffu, rB0, d);
                eA1 += __shfl_xor_sync(0xffffffffu, eA1, d);
                eB1 += __shfl_xor_sync(0xffffffffu, eB1, d);
                rA1 += __shfl_xor_sync(0xffffffffu, rA1, d);
                rB1 += __shfl_xor_sync(0xffffffffu, rB1, d);
            }
            if ((lane & 3) == 0) {
                int h0 = wn >> 5;
                if (gm0 < M) {
                    el[(size_t)gm0 * 4 + h0]     = eA0;
                    el[(size_t)gm0 * 4 + h0 + 1] = eB0;
                    if (gm0 < n_er) {
                        er[(size_t)gm0 * 4 + h0]     = rA0;
                        er[(size_t)gm0 * 4 + h0 + 1] = rB0;
                    }
                }
                if (gm1 < M) {
                    el[(size_t)gm1 * 4 + h0]     = eA1;
                    el[(size_t)gm1 * 4 + h0 + 1] = eB1;
                    if (gm1 < n_er) {
                        er[(size_t)gm1 * 4 + h0]     = rA1;
                        er[(size_t)gm1 * 4 + h0 + 1] = rB1;
                    }
                }
            }
        }
    }
}

// ---------------- CSR build (batched over relations) ----------------
__global__ void fill_int_kernel(int* p, int n, int v) {
    int i = blockIdx.x * blockDim.x + threadIdx.x;
    if (i < n) p[i] = v;
}
__global__ void fill_uint_kernel(unsigned* p, int n, unsigned v) {
    int i = blockIdx.x * blockDim.x + threadIdx.x;
    if (i < n) p[i] = v;
}
__global__ void hist_kernel(const int* __restrict__ dstAll, int E, int* __restrict__ cnt) {
    int j = blockIdx.y;
    int e = blockIdx.x * blockDim.x + threadIdx.x;
    if (e < E) atomicAdd(&cnt[j * N_DST0 + dstAll[(size_t)j * E + e]], 1);
}
__global__ void scan_kernel(const int* __restrict__ cntAll, int* __restrict__ offsAll, int n) {
    const int* cnt = cntAll + blockIdx.x * N_DST0;
    int* offs = offsAll + blockIdx.x * (N_DST0 + 1);
    __shared__ int wsum[32];
    __shared__ int running_s;
    if (threadIdx.x == 0) running_s = 0;
    __syncthreads();
    int lane = threadIdx.x & 31, wid = threadIdx.x >> 5;
    for (int base = 0; base < n; base += 1024) {
        int i = base + (int)threadIdx.x;
        int v = (i < n) ? cnt[i] : 0;
        int x = v;
#pragma unroll
        for (int d = 1; d < 32; d <<= 1) {
            int t = __shfl_up_sync(0xffffffffu, x, d);
            if (lane >= d) x += t;
        }
        if (lane == 31) wsum[wid] = x;
        __syncthreads();
        if (wid == 0) {
            int y = wsum[lane];
#pragma unroll
            for (int d = 1; d < 32; d <<= 1) {
                int t = __shfl_up_sync(0xffffffffu, y, d);
                if (lane >= d) y += t;
            }
            wsum[lane] = y;
        }
        __syncthreads();
        int incl = x + (wid ? wsum[wid - 1] : 0);
        int r = running_s;
        if (i < n) offs[i] = r + (incl - v);
        int total = wsum[31];
        __syncthreads();
        if (threadIdx.x == 0) running_s = r + total;
        __syncthreads();
    }
    if (threadIdx.x == 0) offs[n] = running_s;
}
__global__ void copy_off_kernel(const int* __restrict__ offs, int* __restrict__ cur, int n) {
    int j = blockIdx.y;
    int i = blockIdx.x * blockDim.x + threadIdx.x;
    if (i < n) cur[j * N_DST0 + i] = offs[j * (N_DST0 + 1) + i];
}
__global__ void scatter_kernel(const int* __restrict__ dstAll, int E,
                               int* __restrict__ cur, int* __restrict__ eperm) {
    int j = blockIdx.y;
    int e = blockIdx.x * blockDim.x + threadIdx.x;
    if (e < E) {
        int pos = atomicAdd(&cur[j * N_DST0 + dstAll[(size_t)j * E + e]], 1);
        eperm[(size_t)j * E0 + pos] = e;
    }
}
__global__ void edge_max_kernel(const int* __restrict__ srcAll, const int* __restrict__ dstAll,
                                const float* __restrict__ el, const float* __restrict__ er,
                                unsigned* __restrict__ menc, int E, int n_src, int n_dst)
{
    int j = blockIdx.y;
    int e = blockIdx.x * blockDim.x + threadIdx.x;
    if (e >= E) return;
    int s = srcAll[(size_t)j * E + e], d = dstAll[(size_t)j * E + e];
    float4 L = *(const float4*)(el + ((size_t)j * n_src + s) * 4);
    float4 R = *(const float4*)(er + ((size_t)j * n_dst + d) * 4);
    float lv[4] = {L.x, L.y, L.z, L.w};
    float rv[4] = {R.x, R.y, R.z, R.w};
    unsigned* mj = menc + (size_t)j * N_DST0 * 4;
#pragma unroll
    for (int h = 0; h < 4; h++) {
        float v = lv[h] + rv[h];
        v = v > 0.f ? v : NEG_SLOPE * v;
        atomicMax(&mj[(size_t)d * 4 + h], enc_f(v));
    }
}

// ---------------- aggregation: one block per dst node, all relations ----------------
__global__ void aggregate_all_kernel(
    const __half* __restrict__ Hs, int hsrows,
    const float* __restrict__ el, const float* __restrict__ er,
    const unsigned* __restrict__ menc,
    const int* __restrict__ offs, const int* __restrict__ eperm,
    const int* __restrict__ srcAll, int E,
    const float* __restrict__ b, int n_dst, float* __restrict__ out)
{
    int nd = blockIdx.x;
    int t = threadIdx.x;
    int h = t >> 5;
    __shared__ int   s_src[128];
    __shared__ float s_w[4][128];
    float total = 0.f;

    for (int j = 0; j < T_REL; j++) {
        const __half* Hj = Hs + (size_t)j * hsrows * HID;
        const float* elj = el + (size_t)j * hsrows * 4;
        const float* erj = er + (size_t)j * n_dst * 4;
        const unsigned* mj = menc + (size_t)j * N_DST0 * 4;
        const int* offj = offs + j * (N_DST0 + 1);
        const int* epj  = eperm + (size_t)j * E0;
        const int* sj   = srcAll + (size_t)j * E;

        total += b[j * HID + t];
        int o0 = offj[nd], o1 = offj[nd + 1];
        int cnt = o1 - o0;
        if (cnt == 0) continue;

        float m_all[4], er_all[4];
        {
            float4 e4 = *(const float4*)(erj + (size_t)nd * 4);
            er_all[0] = e4.x; er_all[1] = e4.y; er_all[2] = e4.z; er_all[3] = e4.w;
            uint4 m4 = *(const uint4*)(mj + (size_t)nd * 4);
            m_all[0] = dec_f(m4.x); m_all[1] = dec_f(m4.y);
            m_all[2] = dec_f(m4.z); m_all[3] = dec_f(m4.w);
        }
        float acc = 0.f, ssum = 0.f;
        for (int c0 = 0; c0 < cnt; c0 += 128) {
            int k = c0 + t;
            if (k < cnt) {
                int e = epj[o0 + k];
                int s = sj[e];
                s_src[t] = s;
                float4 L = *(const float4*)(elj + (size_t)s * 4);
                float lv[4] = {L.x, L.y, L.z, L.w};
#pragma unroll
                for (int hh = 0; hh < 4; hh++) {
                    float v = lv[hh] + er_all[hh];
                    v = v > 0.f ? v : NEG_SLOPE * v;
                    s_w[hh][t] = __expf(v - m_all[hh]);
                }
            }
            __syncthreads();
            int len = min(128, cnt - c0);
            const float* wrow = s_w[h];
#pragma unroll 4
            for (int k2 = 0; k2 < len; k2++) {
                float w = wrow[k2];
                float x = __half2float(Hj[(size_t)s_src[k2] * HID + t]);
                acc += w * x;
                ssum += w;
            }
            __syncthreads();
        }
        total += acc / ssum;
    }
    out[(size_t)nd * HID + t] += total;
}

// ---------------- column norm + activation (+ bf16 split output) ----------------
__global__ void colstat_zero_kernel() {
    int t = threadIdx.x;
    g_colsum[t] = 0.0; g_colsq[t] = 0.0;
}
__global__ void colstat_partial_kernel(const float* __restrict__ X, int nrows) {
    int t = threadIdx.x;
    int r0 = blockIdx.x * 256;
    int r1 = min(r0 + 256, nrows);
    float fs = 0.f, fq = 0.f;
    for (int r = r0; r < r1; r++) {
        float v = X[(size_t)r * HID + t];
        fs += v; fq += v * v;
    }
    atomicAdd(&g_colsum[t], (double)fs);
    atomicAdd(&g_colsq[t], (double)fq);
}
__global__ void colstat_final_kernel(int nrows) {
    int t = threadIdx.x;
    double inv = 1.0 / (double)nrows;
    double mean = g_colsum[t] * inv;
    double var = g_colsq[t] * inv - mean * mean;
    g_mean[t] = (float)mean;
    g_rstd[t] = (float)(1.0 / sqrt(var + (double)EPS_LN));
}
__global__ void norm_act_split_kernel(const float* __restrict__ X,
                                      const float* __restrict__ g,
                                      const float* __restrict__ be,
                                      bf16* __restrict__ hi, bf16* __restrict__ lo,
                                      int nrows, int act)
{
    int idx = blockIdx.x * blockDim.x + threadIdx.x;
    if (idx >= nrows * HID) return;
    int t = idx & (HID - 1);
    float v = (X[idx] - g_mean[t]) * g_rstd[t] * g[t] + be[t];
    if (act) v = v > 0.f ? v : 0.f;
    else     v = v > 0.f ? v : expm1f(v);
    bf16 h = __float2bfloat16(v);
    hi[idx] = h;
    lo[idx] = __float2bfloat16(v - __bfloat162float(h));
}

// ---------------- host orchestration ----------------
static inline void* sym(const void* s) { void* p = nullptr; cudaGetSymbolAddress(&p, s); return p; }

static void set_smem_attrs() {
    cudaFuncSetAttribute(mma_gemm2<true,  false, true >, cudaFuncAttributeMaxDynamicSharedMemorySize, SMEM_BYTES);
    cudaFuncSetAttribute(mma_gemm2<false, true,  false>, cudaFuncAttributeMaxDynamicSharedMemorySize, SMEM_BYTES);
}

static void run_layer(const bf16* Ahi, const bf16* Alo, int n_src, int n_dst, int Kdim,
                      const bf16* WtHi, const bf16* WtLo,
                      const bf16* WsHi, const bf16* WsLo,
                      const float* alpha_l, const float* alpha_r,
                      const float* b, const float* bs,
                      const float* gamma, const float* beta,
                      const int* srcAll, const int* dstAll, int E,
                      __half* Hs, float* elbuf, float* erbuf,
                      float* accbuf, bf16* outhi, bf16* outlo)
{
    int* cnt = (int*)sym(g_cnt);
    int* offs = (int*)sym(g_offs);
    int* cur = (int*)sym(g_cur);
    int* eperm = (int*)sym(g_eperm);
    unsigned* menc = (unsigned*)sym(g_menc);

    fill_int_kernel<<<(T_REL * N_DST0 + 255) / 256, 256>>>(cnt, T_REL * N_DST0, 0);
    { dim3 grid((E + 255) / 256, T_REL);
      hist_kernel<<<grid, 256>>>(dstAll, E, cnt); }
    scan_kernel<<<T_REL, 1024>>>(cnt, offs, n_dst);

    {   // Hs = A @ W[j] for all relations, fp16 out, with el/er epilogue
        dim3 grid((n_src + 127) / 128, T_REL);
        mma_gemm2<true, false, true><<<grid, 256, SMEM_BYTES>>>(
            Ahi, Alo, WtHi, WtLo, nullptr, Hs,
            alpha_l, alpha_r, elbuf, erbuf, n_src, HID, Kdim, n_dst);
    }

    { dim3 grid((n_dst + 255) / 256, T_REL);
      copy_off_kernel<<<grid, 256>>>(offs, cur, n_dst); }
    { dim3 grid((E + 255) / 256, T_REL);
      scatter_kernel<<<grid, 256>>>(dstAll, E, cur, eperm); }
    fill_uint_kernel<<<(T_REL * N_DST0 * 4 + 255) / 256, 256>>>(menc, T_REL * N_DST0 * 4, ENC_NEG_INF);

    {   // acc = A[:n_dst] @ Ws + bs (fp32 out)
        dim3 grid((n_dst + 127) / 128, 1);
        mma_gemm2<false, true, false><<<grid, 256, SMEM_BYTES>>>(
            Ahi, Alo, WsHi, WsLo, bs, accbuf,
            nullptr, nullptr, nullptr, nullptr, n_dst, HID, Kdim, 0);
    }

    { dim3 grid((E + 255) / 256, T_REL);
      edge_max_kernel<<<grid, 256>>>(srcAll, dstAll, elbuf, erbuf, menc, E, n_src, n_dst); }

    aggregate_all_kernel<<<n_dst, 128>>>(Hs, n_src, elbuf, erbuf, menc, offs, eperm,
                                         srcAll, E, b, n_dst, accbuf);

    colstat_zero_kernel<<<1, 128>>>();
    colstat_partial_kernel<<<(n_dst + 255) / 256, 128>>>(accbuf, n_dst);
    colstat_final_kernel<<<1, 128>>>(n_dst);
    norm_act_split_kernel<<<(n_dst * HID + 255) / 256, 256>>>(accbuf, gamma, beta,
                                                              outhi, outlo, n_dst, 0);
}

extern "C" void kernel_launch(void* const* d_in, const int* in_sizes, int n_in,
                              void* d_out, int out_size)
{
    (void)in_sizes; (void)n_in; (void)out_size;
    const float* x   = (const float*)d_in[0];
    const float* W0  = (const float*)d_in[1];
    const float* al0 = (const float*)d_in[2];
    const float* ar0 = (const float*)d_in[3];
    const float* b0  = (const float*)d_in[4];
    const float* Ws0 = (const float*)d_in[5];
    const float* bs0 = (const float*)d_in[6];
    const float* g0  = (const float*)d_in[7];
    const float* be0 = (const float*)d_in[8];
    const float* W1  = (const float*)d_in[9];
    const float* al1 = (const float*)d_in[10];
    const float* ar1 = (const float*)d_in[11];
    const float* b1  = (const float*)d_in[12];
    const float* Ws1 = (const float*)d_in[13];
    const float* bs1 = (const float*)d_in[14];
    const float* g1  = (const float*)d_in[15];
    const float* be1 = (const float*)d_in[16];
    const float* Wm1 = (const float*)d_in[17];
    const float* bm1 = (const float*)d_in[18];
    const float* gm  = (const float*)d_in[19];
    const float* bem = (const float*)d_in[20];
    const float* Wm2 = (const float*)d_in[21];
    const float* bm2 = (const float*)d_in[22];
    const int* src0  = (const int*)d_in[23];
    const int* dst0  = (const int*)d_in[24];
    const int* src1  = (const int*)d_in[25];
    const int* dst1  = (const int*)d_in[26];
    float* out = (float*)d_out;

    __half* Hs0 = (__half*)sym(g_Hs0);
    __half* Hs1 = (__half*)sym(g_Hs1);
    float* el0p = (float*)sym(g_el0);
    float* er0p = (float*)sym(g_er0);
    float* el1p = (float*)sym(g_el1);
    float* er1p = (float*)sym(g_er1);
    float* acc0 = (float*)sym(g_acc0);
    float* acc1 = (float*)sym(g_acc1);
    float* mlp  = (float*)sym(g_mlp);
    bf16* xhi = (bf16*)sym(g_xhi);
    bf16* xlo = (bf16*)sym(g_xlo);
    bf16* shi = (bf16*)sym(g_shi);
    bf16* slo = (bf16*)sym(g_slo);
    bf16* thi = (bf16*)sym(g_thi);
    bf16* tlo = (bf16*)sym(g_tlo);
    bf16* wthi = (bf16*)sym(g_wthi);
    bf16* wtlo = (bf16*)sym(g_wtlo);

    set_smem_attrs();

    {
        dim3 g((T_REL * HID * IN_DIM + 255) / 256, 6);
        splitw_all_kernel<<<g, 256>>>(W0, Ws0, W1, Ws1, Wm1, Wm2, wthi, wtlo);
    }
    {
        size_t n = (size_t)N_SRC0 * IN_DIM;
        split_kernel<<<(unsigned)((n + 255) / 256), 256>>>(x, xhi, xlo, n);
    }

    // Layer 0
    run_layer(xhi, xlo, N_SRC0, N_DST0, IN_DIM,
              wthi + W0T_OFF, wtlo + W0T_OFF, wthi + WS0T_OFF, wtlo + WS0T_OFF,
              al0, ar0, b0, bs0, g0, be0,
              src0, dst0, E0, Hs0, el0p, er0p, acc0, shi, slo);

    // Layer 1
    run_layer(shi, slo, N_DST0, N_DST1, HID,
              wthi + W1T_OFF, wtlo + W1T_OFF, wthi + WS1T_OFF, wtlo + WS1T_OFF,
              al1, ar1, b1, bs1, g1, be1,
              src1, dst1, E1, Hs1, el1p, er1p, acc1, thi, tlo);

    // MLP
    {
        dim3 grid((N_DST1 + 127) / 128, 1);
        mma_gemm2<false, true, false><<<grid, 256, SMEM_BYTES>>>(
            thi, tlo, wthi + WM1T_OFF, wtlo + WM1T_OFF, bm1, mlp,
            nullptr, nullptr, nullptr, nullptr, N_DST1, HID, HID, 0);
    }
    colstat_zero_kernel<<<1, 128>>>();
    colstat_partial_kernel<<<(N_DST1 + 255) / 256, 128>>>(mlp, N_DST1);
    colstat_final_kernel<<<1, 128>>>(N_DST1);
    norm_act_split_kernel<<<(N_DST1 * HID + 255) / 256, 256>>>(mlp, gm, bem, shi, slo, N_DST1, 1);
    {
        size_t n = (size_t)N_DST1 * HID;
        (void)n;
    }
    {
        dim3 grid((N_DST1 + 127) / 128, (OUT_DIM + 127) / 128);
        mma_gemm2<false, true, false><<<grid, 256, SMEM_BYTES>>>(
            shi, slo, wthi + WM2T_OFF, wtlo + WM2T_OFF, bm2, out,
            nullptr, nullptr, nullptr, nullptr, N_DST1, OUT_DIM, HID, 0);
    }
}

// round 8
// speedup vs baseline: 1.7702x; 1.1610x over previous
#include <cuda_runtime.h>
#include <cuda_bf16.h>
#include <cuda_fp16.h>
#include <cstdint>

#define N_SRC0 120000
#define N_DST0 40000
#define N_DST1 10000
#define T_REL  5
#define HID    128
#define IN_DIM 256
#define OUT_DIM 153
#define E0 800000
#define E1 300000
#define NEG_SLOPE 0.2f
#define EPS_LN 1e-5f

typedef __nv_bfloat16 bf16;

// ---------------- static device scratch ----------------
__device__ __align__(128) __half g_Hs0[(size_t)T_REL * N_SRC0 * HID];
__device__ __align__(128) __half g_Hs1[(size_t)T_REL * N_DST0 * HID];
__device__ __align__(16)  float g_el0[(size_t)T_REL * N_SRC0 * 4];
__device__ __align__(16)  float g_er0[(size_t)T_REL * N_DST0 * 4];
__device__ __align__(16)  float g_el1[(size_t)T_REL * N_DST0 * 4];
__device__ __align__(16)  float g_er1[(size_t)T_REL * N_DST1 * 4];
__device__ __align__(128) float g_acc0[(size_t)N_DST0 * HID];
__device__ __align__(128) float g_acc1[(size_t)N_DST1 * HID];
__device__ __align__(128) float g_mlp[(size_t)N_DST1 * HID];
__device__ int      g_cnt[T_REL * N_DST0];
__device__ int      g_offs[T_REL * (N_DST0 + 1)];
__device__ int      g_cur[T_REL * N_DST0];
__device__ int      g_eperm[T_REL * E0];      // stores SRC node id (not edge id)
__device__ unsigned g_menc[(size_t)T_REL * N_DST0 * 4];
__device__ double   g_colsum[HID];
__device__ double   g_colsq[HID];
__device__ float    g_mean[HID];
__device__ float    g_rstd[HID];
__device__ __align__(128) bf16 g_xhi[(size_t)N_SRC0 * IN_DIM];
__device__ __align__(128) bf16 g_xlo[(size_t)N_SRC0 * IN_DIM];
__device__ __align__(128) bf16 g_shi[(size_t)N_DST0 * HID];
__device__ __align__(128) bf16 g_slo[(size_t)N_DST0 * HID];
__device__ __align__(128) bf16 g_thi[(size_t)N_DST1 * HID];
__device__ __align__(128) bf16 g_tlo[(size_t)N_DST1 * HID];
#define W0T_OFF   0
#define WS0T_OFF  163840
#define W1T_OFF   196608
#define WS1T_OFF  278528
#define WM1T_OFF  294912
#define WM2T_OFF  311296
#define WT_TOTAL  330880
__device__ __align__(128) bf16 g_wthi[WT_TOTAL];
__device__ __align__(128) bf16 g_wtlo[WT_TOTAL];

// ---------------- helpers ----------------
__device__ __forceinline__ unsigned enc_f(float f) {
    unsigned u = __float_as_uint(f);
    return (u & 0x80000000u) ? ~u : (u | 0x80000000u);
}
__device__ __forceinline__ float dec_f(unsigned e) {
    return (e & 0x80000000u) ? __uint_as_float(e ^ 0x80000000u)
                             : __uint_as_float(~e);
}
#define ENC_NEG_INF 0x007FFFFFu

__device__ __forceinline__ void cp_async16(uint32_t dst, const void* src, int sz) {
    asm volatile("cp.async.cg.shared.global [%0], [%1], 16, %2;\n"
                 :: "r"(dst), "l"(src), "r"(sz));
}
__device__ __forceinline__ void cp_commit() {
    asm volatile("cp.async.commit_group;\n");
}
__device__ __forceinline__ void ldsm4(uint32_t* r, uint32_t addr) {
    asm volatile("ldmatrix.sync.aligned.m8n8.x4.shared.b16 {%0,%1,%2,%3}, [%4];"
        : "=r"(r[0]), "=r"(r[1]), "=r"(r[2]), "=r"(r[3]) : "r"(addr));
}
__device__ __forceinline__ void mma16816(float* c, const uint32_t* a, uint32_t b0, uint32_t b1) {
    asm volatile("mma.sync.aligned.m16n8k16.row.col.f32.bf16.bf16.f32 "
        "{%0,%1,%2,%3}, {%4,%5,%6,%7}, {%8,%9}, {%0,%1,%2,%3};"
        : "+f"(c[0]), "+f"(c[1]), "+f"(c[2]), "+f"(c[3])
        : "r"(a[0]), "r"(a[1]), "r"(a[2]), "r"(a[3]), "r"(b0), "r"(b1));
}

// ---------------- split kernels ----------------
__global__ void split_kernel(const float* __restrict__ X, bf16* __restrict__ hi,
                             bf16* __restrict__ lo, size_t n)
{
    size_t i = (size_t)blockIdx.x * blockDim.x + threadIdx.x;
    if (i >= n) return;
    float v = X[i];
    bf16 h = __float2bfloat16(v);
    hi[i] = h;
    lo[i] = __float2bfloat16(v - __bfloat162float(h));
}
__global__ void splitw_all_kernel(
    const float* __restrict__ W0, const float* __restrict__ Ws0,
    const float* __restrict__ W1, const float* __restrict__ Ws1,
    const float* __restrict__ Wm1, const float* __restrict__ Wm2,
    bf16* __restrict__ hiT, bf16* __restrict__ loT)
{
    int seg = blockIdx.y;
    const float* W; int K, N, nrel, off;
    switch (seg) {
        case 0:  W = W0;  K = IN_DIM; N = HID;     nrel = T_REL; off = W0T_OFF;  break;
        case 1:  W = Ws0; K = IN_DIM; N = HID;     nrel = 1;     off = WS0T_OFF; break;
        case 2:  W = W1;  K = HID;    N = HID;     nrel = T_REL; off = W1T_OFF;  break;
        case 3:  W = Ws1; K = HID;    N = HID;     nrel = 1;     off = WS1T_OFF; break;
        case 4:  W = Wm1; K = HID;    N = HID;     nrel = 1;     off = WM1T_OFF; break;
        default: W = Wm2; K = HID;    N = OUT_DIM; nrel = 1;     off = WM2T_OFF; break;
    }
    int total = nrel * N * K;
    int idx = blockIdx.x * blockDim.x + threadIdx.x;
    if (idx >= total) return;
    int j = idx / (N * K);
    int rem = idx - j * (N * K);
    int n = rem / K, k = rem - n * K;
    float v = W[((size_t)j * K + k) * N + n];
    bf16 h = __float2bfloat16(v);
    hiT[off + idx] = h;
    loT[off + idx] = __float2bfloat16(v - __bfloat162float(h));
}

// ---------------- fused bf16x3 MMA GEMM (+ optional attn-logit epilogue) ------
#define GSTRIDE  40
#define SM_TILE  (128 * GSTRIDE)
#define SM_AHI   0
#define SM_ALO   SM_TILE
#define SM_BHI   (2 * SM_TILE)
#define SM_BLO   (3 * SM_TILE)
#define SM_STAGE (4 * SM_TILE)
#define SMEM_BYTES (2 * SM_STAGE * 2)

template<bool REL, bool HASBIAS, bool EPI>
__global__ void __launch_bounds__(256, 2) mma_gemm2(
    const bf16* __restrict__ Ahi, const bf16* __restrict__ Alo,
    const bf16* __restrict__ BThi, const bf16* __restrict__ BTlo,
    const float* __restrict__ bias, void* __restrict__ Cv,
    const float* __restrict__ al, const float* __restrict__ ar,
    float* __restrict__ el, float* __restrict__ er,
    int M, int N, int K, int n_er)
{
    extern __shared__ bf16 sm[];

    __half* Ch = (__half*)Cv;
    float*  Cf = (float*)Cv;

    int bm0, bn0, ldc;
    if (REL) {
        int j = blockIdx.x;
        bm0 = blockIdx.y * 128;
        BThi += (size_t)j * 128 * K;
        BTlo += (size_t)j * 128 * K;
        Ch   += (size_t)j * M * 128;
        if (EPI) {
            al += (size_t)j * HID;  ar += (size_t)j * HID;
            el += (size_t)j * M * 4; er += (size_t)j * n_er * 4;
        }
        bn0 = 0; ldc = 128; N = 128;
    } else {
        bm0 = blockIdx.x * 128;
        bn0 = blockIdx.y * 128; ldc = N;
    }

    int tid = threadIdx.x, lane = tid & 31, warp = tid >> 5;
    int wm = (warp & 3) * 32, wn = (warp >> 2) * 64;

    int kc = K >> 5;

    int ldrow = tid >> 2;
    int ldcol = (tid & 3) << 3;

    uint32_t s0 = (uint32_t)__cvta_generic_to_shared(sm);

    int mrowA = lane & 15, mcolA = (lane >> 4) << 3;
    int mrowB = (lane & 7) | ((lane >> 4) << 3);
    int mcolB = ((lane >> 3) & 1) << 3;

    float acc[2][8][4];
#pragma unroll
    for (int a = 0; a < 2; a++)
#pragma unroll
        for (int b = 0; b < 8; b++)
#pragma unroll
            for (int c = 0; c < 4; c++) acc[a][b][c] = 0.f;

#define LOAD_STAGE(IT, ST) do {                                                  \
    int kk_ = (IT) << 5;                                                         \
    uint32_t sb_ = s0 + (uint32_t)(ST) * (SM_STAGE * 2);                         \
    _Pragma("unroll")                                                            \
    for (int hh = 0; hh < 2; hh++) {                                             \
        int row = ldrow + hh * 64;                                               \
        int gm = bm0 + row;                                                      \
        int ok = gm < M;                                                         \
        size_t aoff = (size_t)(ok ? gm : 0) * K + kk_ + ldcol;                   \
        cp_async16(sb_ + (SM_AHI + row * GSTRIDE + ldcol) * 2, Ahi + aoff, ok ? 16 : 0); \
        cp_async16(sb_ + (SM_ALO + row * GSTRIDE + ldcol) * 2, Alo + aoff, ok ? 16 : 0); \
        int gn = bn0 + row;                                                      \
        int okb = gn < N;                                                        \
        size_t boff = (size_t)(okb ? gn : 0) * K + kk_ + ldcol;                  \
        cp_async16(sb_ + (SM_BHI + row * GSTRIDE + ldcol) * 2, BThi + boff, okb ? 16 : 0); \
        cp_async16(sb_ + (SM_BLO + row * GSTRIDE + ldcol) * 2, BTlo + boff, okb ? 16 : 0); \
    }                                                                            \
    cp_commit();                                                                 \
} while (0)

    LOAD_STAGE(0, 0);
    for (int it = 0; it < kc; it++) {
        int st = it & 1;
        if (it + 1 < kc) {
            LOAD_STAGE(it + 1, st ^ 1);
            asm volatile("cp.async.wait_group 1;\n" ::: "memory");
        } else {
            asm volatile("cp.async.wait_group 0;\n" ::: "memory");
        }
        __syncthreads();
        uint32_t base = s0 + (uint32_t)st * (SM_STAGE * 2);
#pragma unroll
        for (int s = 0; s < 2; s++) {
            uint32_t ahi[2][4], alo2[2][4];
#pragma unroll
            for (int mt = 0; mt < 2; mt++) {
                uint32_t ra = (wm + mt * 16 + mrowA) * GSTRIDE + s * 16 + mcolA;
                ldsm4(ahi[mt],  base + (SM_AHI + ra) * 2);
                ldsm4(alo2[mt], base + (SM_ALO + ra) * 2);
            }
#pragma unroll
            for (int np = 0; np < 4; np++) {
                uint32_t bh[4];
                ldsm4(bh, base + (SM_BHI + (wn + np * 16 + mrowB) * GSTRIDE + s * 16 + mcolB) * 2);
#pragma unroll
                for (int mt = 0; mt < 2; mt++) {
                    mma16816(acc[mt][2 * np],     ahi[mt],  bh[0], bh[1]);
                    mma16816(acc[mt][2 * np + 1], ahi[mt],  bh[2], bh[3]);
                    mma16816(acc[mt][2 * np],     alo2[mt], bh[0], bh[1]);
                    mma16816(acc[mt][2 * np + 1], alo2[mt], bh[2], bh[3]);
                }
            }
#pragma unroll
            for (int np = 0; np < 4; np++) {
                uint32_t bl[4];
                ldsm4(bl, base + (SM_BLO + (wn + np * 16 + mrowB) * GSTRIDE + s * 16 + mcolB) * 2);
#pragma unroll
                for (int mt = 0; mt < 2; mt++) {
                    mma16816(acc[mt][2 * np],     ahi[mt], bl[0], bl[1]);
                    mma16816(acc[mt][2 * np + 1], ahi[mt], bl[2], bl[3]);
                }
            }
        }
        __syncthreads();
    }
#undef LOAD_STAGE

    int trow = lane >> 2, tcol = (lane & 3) << 1;
#pragma unroll
    for (int mt = 0; mt < 2; mt++) {
        int gm0 = bm0 + wm + mt * 16 + trow;
        int gm1 = gm0 + 8;
#pragma unroll
        for (int nt = 0; nt < 8; nt++) {
            int gn = bn0 + wn + nt * 8 + tcol;
            float* cr = acc[mt][nt];
            if (REL) {
                if (gm0 < M) {
                    Ch[(size_t)gm0 * ldc + gn]     = __float2half(cr[0]);
                    Ch[(size_t)gm0 * ldc + gn + 1] = __float2half(cr[1]);
                }
                if (gm1 < M) {
                    Ch[(size_t)gm1 * ldc + gn]     = __float2half(cr[2]);
                    Ch[(size_t)gm1 * ldc + gn + 1] = __float2half(cr[3]);
                }
            } else {
                bool okn0 = gn < N, okn1 = gn + 1 < N;
                float b0a = 0.f, b1a = 0.f;
                if (HASBIAS) {
                    if (okn0) b0a = bias[gn];
                    if (okn1) b1a = bias[gn + 1];
                }
                if (gm0 < M) {
                    if (okn0) Cf[(size_t)gm0 * ldc + gn]     = cr[0] + b0a;
                    if (okn1) Cf[(size_t)gm0 * ldc + gn + 1] = cr[1] + b1a;
                }
                if (gm1 < M) {
                    if (okn0) Cf[(size_t)gm1 * ldc + gn]     = cr[2] + b0a;
                    if (okn1) Cf[(size_t)gm1 * ldc + gn + 1] = cr[3] + b1a;
                }
            }
        }
        if (EPI) {
            float eA0 = 0.f, eB0 = 0.f, rA0 = 0.f, rB0 = 0.f;
            float eA1 = 0.f, eB1 = 0.f, rA1 = 0.f, rB1 = 0.f;
#pragma unroll
            for (int nt = 0; nt < 8; nt++) {
                int gn = wn + nt * 8 + tcol;
                float a0v = al[gn], a1v = al[gn + 1];
                float r0v = ar[gn], r1v = ar[gn + 1];
                float* cr = acc[mt][nt];
                float c0 = cr[0] * a0v + cr[1] * a1v;
                float c1 = cr[2] * a0v + cr[3] * a1v;
                float d0 = cr[0] * r0v + cr[1] * r1v;
                float d1 = cr[2] * r0v + cr[3] * r1v;
                if (nt < 4) { eA0 += c0; eA1 += c1; rA0 += d0; rA1 += d1; }
                else        { eB0 += c0; eB1 += c1; rB0 += d0; rB1 += d1; }
            }
#pragma unroll
            for (int d = 1; d < 4; d <<= 1) {
                eA0 += __shfl_xor_sync(0xffffffffu, eA0, d);
                eB0 += __shfl_xor_sync(0xffffffffu, eB0, d);
                rA0 += __shfl_xor_sync(0xffffffffu, rA0, d);
                rB0 += __shfl_xor_sync(0xffffffffu, rB0, d);
                eA1 += __shfl_xor_sync(0xffffffffu, eA1, d);
                eB1 += __shfl_xor_sync(0xffffffffu, eB1, d);
                rA1 += __shfl_xor_sync(0xffffffffu, rA1, d);
                rB1 += __shfl_xor_sync(0xffffffffu, rB1, d);
            }
            if ((lane & 3) == 0) {
                int h0 = wn >> 5;
                if (gm0 < M) {
                    el[(size_t)gm0 * 4 + h0]     = eA0;
                    el[(size_t)gm0 * 4 + h0 + 1] = eB0;
                    if (gm0 < n_er) {
                        er[(size_t)gm0 * 4 + h0]     = rA0;
                        er[(size_t)gm0 * 4 + h0 + 1] = rB0;
                    }
                }
                if (gm1 < M) {
                    el[(size_t)gm1 * 4 + h0]     = eA1;
                    el[(size_t)gm1 * 4 + h0 + 1] = eB1;
                    if (gm1 < n_er) {
                        er[(size_t)gm1 * 4 + h0]     = rA1;
                        er[(size_t)gm1 * 4 + h0 + 1] = rB1;
                    }
                }
            }
        }
    }
}

// ---------------- CSR build ----------------
__global__ void fill_int_kernel(int* p, int n, int v) {
    int i = blockIdx.x * blockDim.x + threadIdx.x;
    if (i < n) p[i] = v;
}
__global__ void fill_uint_kernel(unsigned* p, int n, unsigned v) {
    int i = blockIdx.x * blockDim.x + threadIdx.x;
    if (i < n) p[i] = v;
}
__global__ void hist_kernel(const int* __restrict__ dstAll, int E, int* __restrict__ cnt) {
    int j = blockIdx.y;
    int e = blockIdx.x * blockDim.x + threadIdx.x;
    if (e < E) atomicAdd(&cnt[j * N_DST0 + dstAll[(size_t)j * E + e]], 1);
}
__global__ void scan_kernel(const int* __restrict__ cntAll, int* __restrict__ offsAll,
                            int* __restrict__ curAll, int n) {
    const int* cnt = cntAll + blockIdx.x * N_DST0;
    int* offs = offsAll + blockIdx.x * (N_DST0 + 1);
    int* cur  = curAll + blockIdx.x * N_DST0;
    __shared__ int wsum[32];
    __shared__ int running_s;
    if (threadIdx.x == 0) running_s = 0;
    __syncthreads();
    int lane = threadIdx.x & 31, wid = threadIdx.x >> 5;
    for (int base = 0; base < n; base += 1024) {
        int i = base + (int)threadIdx.x;
        int v = (i < n) ? cnt[i] : 0;
        int x = v;
#pragma unroll
        for (int d = 1; d < 32; d <<= 1) {
            int t = __shfl_up_sync(0xffffffffu, x, d);
            if (lane >= d) x += t;
        }
        if (lane == 31) wsum[wid] = x;
        __syncthreads();
        if (wid == 0) {
            int y = wsum[lane];
#pragma unroll
            for (int d = 1; d < 32; d <<= 1) {
                int t = __shfl_up_sync(0xffffffffu, y, d);
                if (lane >= d) y += t;
            }
            wsum[lane] = y;
        }
        __syncthreads();
        int incl = x + (wid ? wsum[wid - 1] : 0);
        int r = running_s;
        if (i < n) { int o = r + (incl - v); offs[i] = o; cur[i] = o; }
        int total = wsum[31];
        __syncthreads();
        if (threadIdx.x == 0) running_s = r + total;
        __syncthreads();
    }
    if (threadIdx.x == 0) offs[n] = running_s;
}
__global__ void scatter_max_kernel(const int* __restrict__ srcAll,
                                   const int* __restrict__ dstAll, int E,
                                   int* __restrict__ cur, int* __restrict__ eperm,
                                   const float* __restrict__ el, const float* __restrict__ er,
                                   unsigned* __restrict__ menc, int n_src, int n_dst)
{
    int j = blockIdx.y;
    int e = blockIdx.x * blockDim.x + threadIdx.x;
    if (e >= E) return;
    int s = srcAll[(size_t)j * E + e];
    int d = dstAll[(size_t)j * E + e];
    int pos = atomicAdd(&cur[j * N_DST0 + d], 1);
    eperm[(size_t)j * E0 + pos] = s;
    float4 L = *(const float4*)(el + ((size_t)j * n_src + s) * 4);
    float4 R = *(const float4*)(er + ((size_t)j * n_dst + d) * 4);
    float lv[4] = {L.x, L.y, L.z, L.w};
    float rv[4] = {R.x, R.y, R.z, R.w};
    unsigned* mj = menc + (size_t)j * N_DST0 * 4;
#pragma unroll
    for (int h = 0; h < 4; h++) {
        float v = lv[h] + rv[h];
        v = v > 0.f ? v : NEG_SLOPE * v;
        atomicMax(&mj[(size_t)d * 4 + h], enc_f(v));
    }
}

// ---------------- aggregation: one block (64 thr) per dst node, half2 columns --
__global__ void aggregate_all_kernel(
    const __half* __restrict__ Hs, int hsrows,
    const float* __restrict__ el, const float* __restrict__ er,
    const unsigned* __restrict__ menc,
    const int* __restrict__ offs, const int* __restrict__ eperm,
    const float* __restrict__ b, int n_dst, float* __restrict__ out)
{
    int nd = blockIdx.x;
    int t = threadIdx.x;              // 0..63, handles columns 2t, 2t+1
    int h = t >> 4;                   // head of cols 2t,2t+1 (0..3)
    __shared__ int   s_src[64];
    __shared__ float s_w[4][64];
    float2 total = make_float2(0.f, 0.f);

    for (int j = 0; j < T_REL; j++) {
        const __half* Hj = Hs + (size_t)j * hsrows * HID;
        const float* elj = el + (size_t)j * hsrows * 4;
        const float* erj = er + (size_t)j * n_dst * 4;
        const unsigned* mj = menc + (size_t)j * N_DST0 * 4;
        const int* offj = offs + j * (N_DST0 + 1);
        const int* epj  = eperm + (size_t)j * E0;

        float2 bb = *(const float2*)(b + j * HID + 2 * t);
        total.x += bb.x; total.y += bb.y;
        int o0 = offj[nd], o1 = offj[nd + 1];
        int cnt = o1 - o0;
        if (cnt == 0) continue;

        float m_all[4], er_all[4];
        {
            float4 e4 = *(const float4*)(erj + (size_t)nd * 4);
            er_all[0] = e4.x; er_all[1] = e4.y; er_all[2] = e4.z; er_all[3] = e4.w;
            uint4 m4 = *(const uint4*)(mj + (size_t)nd * 4);
            m_all[0] = dec_f(m4.x); m_all[1] = dec_f(m4.y);
            m_all[2] = dec_f(m4.z); m_all[3] = dec_f(m4.w);
        }
        float2 acc = make_float2(0.f, 0.f);
        float ssum = 0.f;
        for (int c0 = 0; c0 < cnt; c0 += 64) {
            int k = c0 + t;
            if (k < cnt) {
                int s = epj[o0 + k];
                s_src[t] = s;
                float4 L = *(const float4*)(elj + (size_t)s * 4);
                float lv[4] = {L.x, L.y, L.z, L.w};
#pragma unroll
                for (int hh = 0; hh < 4; hh++) {
                    float v = lv[hh] + er_all[hh];
                    v = v > 0.f ? v : NEG_SLOPE * v;
                    s_w[hh][t] = __expf(v - m_all[hh]);
                }
            }
            __syncthreads();
            int len = min(64, cnt - c0);
            const float* wrow = s_w[h];
#pragma unroll 4
            for (int k2 = 0; k2 < len; k2++) {
                float w = wrow[k2];
                __half2 x2 = *(const __half2*)(Hj + (size_t)s_src[k2] * HID + 2 * t);
                float2 xf = __half22float2(x2);
                acc.x += w * xf.x;
                acc.y += w * xf.y;
                ssum += w;
            }
            __syncthreads();
        }
        float inv = 1.f / ssum;
        total.x += acc.x * inv;
        total.y += acc.y * inv;
    }
    float2* op = (float2*)(out + (size_t)nd * HID + 2 * t);
    float2 prev = *op;
    prev.x += total.x; prev.y += total.y;
    *op = prev;
}

// ---------------- column norm + activation ----------------
__global__ void colstat_zero_kernel() {
    int t = threadIdx.x;
    g_colsum[t] = 0.0; g_colsq[t] = 0.0;
}
__global__ void colstat_partial_kernel(const float* __restrict__ X, int nrows) {
    int t = threadIdx.x;
    int r0 = blockIdx.x * 256;
    int r1 = min(r0 + 256, nrows);
    float fs = 0.f, fq = 0.f;
    for (int r = r0; r < r1; r++) {
        float v = X[(size_t)r * HID + t];
        fs += v; fq += v * v;
    }
    atomicAdd(&g_colsum[t], (double)fs);
    atomicAdd(&g_colsq[t], (double)fq);
}
__global__ void colstat_final_kernel(int nrows) {
    int t = threadIdx.x;
    double inv = 1.0 / (double)nrows;
    double mean = g_colsum[t] * inv;
    double var = g_colsq[t] * inv - mean * mean;
    g_mean[t] = (float)mean;
    g_rstd[t] = (float)(1.0 / sqrt(var + (double)EPS_LN));
}
__global__ void norm_act_split_kernel(const float* __restrict__ X,
                                      const float* __restrict__ g,
                                      const float* __restrict__ be,
                                      bf16* __restrict__ hi, bf16* __restrict__ lo,
                                      int nrows, int act)
{
    int idx = blockIdx.x * blockDim.x + threadIdx.x;
    if (idx >= nrows * HID) return;
    int t = idx & (HID - 1);
    float v = (X[idx] - g_mean[t]) * g_rstd[t] * g[t] + be[t];
    if (act) v = v > 0.f ? v : 0.f;
    else     v = v > 0.f ? v : expm1f(v);
    bf16 h = __float2bfloat16(v);
    hi[idx] = h;
    lo[idx] = __float2bfloat16(v - __bfloat162float(h));
}

// ---------------- host orchestration ----------------
static inline void* sym(const void* s) { void* p = nullptr; cudaGetSymbolAddress(&p, s); return p; }

static void set_smem_attrs() {
    cudaFuncSetAttribute(mma_gemm2<true,  false, true >, cudaFuncAttributeMaxDynamicSharedMemorySize, SMEM_BYTES);
    cudaFuncSetAttribute(mma_gemm2<false, true,  false>, cudaFuncAttributeMaxDynamicSharedMemorySize, SMEM_BYTES);
}

static void run_layer(const bf16* Ahi, const bf16* Alo, int n_src, int n_dst, int Kdim,
                      const bf16* WtHi, const bf16* WtLo,
                      const bf16* WsHi, const bf16* WsLo,
                      const float* alpha_l, const float* alpha_r,
                      const float* b, const float* bs,
                      const float* gamma, const float* beta,
                      const int* srcAll, const int* dstAll, int E,
                      __half* Hs, float* elbuf, float* erbuf,
                      float* accbuf, bf16* outhi, bf16* outlo)
{
    int* cnt = (int*)sym(g_cnt);
    int* offs = (int*)sym(g_offs);
    int* cur = (int*)sym(g_cur);
    int* eperm = (int*)sym(g_eperm);
    unsigned* menc = (unsigned*)sym(g_menc);

    fill_int_kernel<<<(T_REL * N_DST0 + 255) / 256, 256>>>(cnt, T_REL * N_DST0, 0);
    { dim3 grid((E + 255) / 256, T_REL);
      hist_kernel<<<grid, 256>>>(dstAll, E, cnt); }

    {   // Hs = A @ W[j]^T for all relations (grid.x = relation for A-tile L2 reuse)
        dim3 grid(T_REL, (n_src + 127) / 128);
        mma_gemm2<true, false, true><<<grid, 256, SMEM_BYTES>>>(
            Ahi, Alo, WtHi, WtLo, nullptr, Hs,
            alpha_l, alpha_r, elbuf, erbuf, n_src, HID, Kdim, n_dst);
    }

    scan_kernel<<<T_REL, 1024>>>(cnt, offs, cur, n_dst);
    fill_uint_kernel<<<(T_REL * N_DST0 * 4 + 255) / 256, 256>>>(menc, T_REL * N_DST0 * 4, ENC_NEG_INF);
    { dim3 grid((E + 255) / 256, T_REL);
      scatter_max_kernel<<<grid, 256>>>(srcAll, dstAll, E, cur, eperm,
                                        elbuf, erbuf, menc, n_src, n_dst); }

    {   // acc = A[:n_dst] @ Ws + bs (fp32 out)
        dim3 grid((n_dst + 127) / 128, 1);
        mma_gemm2<false, true, false><<<grid, 256, SMEM_BYTES>>>(
            Ahi, Alo, WsHi, WsLo, bs, accbuf,
            nullptr, nullptr, nullptr, nullptr, n_dst, HID, Kdim, 0);
    }

    aggregate_all_kernel<<<n_dst, 64>>>(Hs, n_src, elbuf, erbuf, menc, offs, eperm,
                                        b, n_dst, accbuf);

    colstat_zero_kernel<<<1, 128>>>();
    colstat_partial_kernel<<<(n_dst + 255) / 256, 128>>>(accbuf, n_dst);
    colstat_final_kernel<<<1, 128>>>(n_dst);
    norm_act_split_kernel<<<(n_dst * HID + 255) / 256, 256>>>(accbuf, gamma, beta,
                                                              outhi, outlo, n_dst, 0);
}

extern "C" void kernel_launch(void* const* d_in, const int* in_sizes, int n_in,
                              void* d_out, int out_size)
{
    (void)in_sizes; (void)n_in; (void)out_size;
    const float* x   = (const float*)d_in[0];
    const float* W0  = (const float*)d_in[1];
    const float* al0 = (const float*)d_in[2];
    const float* ar0 = (const float*)d_in[3];
    const float* b0  = (const float*)d_in[4];
    const float* Ws0 = (const float*)d_in[5];
    const float* bs0 = (const float*)d_in[6];
    const float* g0  = (const float*)d_in[7];
    const float* be0 = (const float*)d_in[8];
    const float* W1  = (const float*)d_in[9];
    const float* al1 = (const float*)d_in[10];
    const float* ar1 = (const float*)d_in[11];
    const float* b1  = (const float*)d_in[12];
    const float* Ws1 = (const float*)d_in[13];
    const float* bs1 = (const float*)d_in[14];
    const float* g1  = (const float*)d_in[15];
    const float* be1 = (const float*)d_in[16];
    const float* Wm1 = (const float*)d_in[17];
    const float* bm1 = (const float*)d_in[18];
    const float* gm  = (const float*)d_in[19];
    const float* bem = (const float*)d_in[20];
    const float* Wm2 = (const float*)d_in[21];
    const float* bm2 = (const float*)d_in[22];
    const int* src0  = (const int*)d_in[23];
    const int* dst0  = (const int*)d_in[24];
    const int* src1  = (const int*)d_in[25];
    const int* dst1  = (const int*)d_in[26];
    float* out = (float*)d_out;

    __half* Hs0 = (__half*)sym(g_Hs0);
    __half* Hs1 = (__half*)sym(g_Hs1);
    float* el0p = (float*)sym(g_el0);
    float* er0p = (float*)sym(g_er0);
    float* el1p = (float*)sym(g_el1);
    float* er1p = (float*)sym(g_er1);
    float* acc0 = (float*)sym(g_acc0);
    float* acc1 = (float*)sym(g_acc1);
    float* mlp  = (float*)sym(g_mlp);
    bf16* xhi = (bf16*)sym(g_xhi);
    bf16* xlo = (bf16*)sym(g_xlo);
    bf16* shi = (bf16*)sym(g_shi);
    bf16* slo = (bf16*)sym(g_slo);
    bf16* thi = (bf16*)sym(g_thi);
    bf16* tlo = (bf16*)sym(g_tlo);
    bf16* wthi = (bf16*)sym(g_wthi);
    bf16* wtlo = (bf16*)sym(g_wtlo);

    set_smem_attrs();

    {
        dim3 g((T_REL * HID * IN_DIM + 255) / 256, 6);
        splitw_all_kernel<<<g, 256>>>(W0, Ws0, W1, Ws1, Wm1, Wm2, wthi, wtlo);
    }
    {
        size_t n = (size_t)N_SRC0 * IN_DIM;
        split_kernel<<<(unsigned)((n + 255) / 256), 256>>>(x, xhi, xlo, n);
    }

    // Layer 0
    run_layer(xhi, xlo, N_SRC0, N_DST0, IN_DIM,
              wthi + W0T_OFF, wtlo + W0T_OFF, wthi + WS0T_OFF, wtlo + WS0T_OFF,
              al0, ar0, b0, bs0, g0, be0,
              src0, dst0, E0, Hs0, el0p, er0p, acc0, shi, slo);

    // Layer 1
    run_layer(shi, slo, N_DST0, N_DST1, HID,
              wthi + W1T_OFF, wtlo + W1T_OFF, wthi + WS1T_OFF, wtlo + WS1T_OFF,
              al1, ar1, b1, bs1, g1, be1,
              src1, dst1, E1, Hs1, el1p, er1p, acc1, thi, tlo);

    // MLP
    {
        dim3 grid((N_DST1 + 127) / 128, 1);
        mma_gemm2<false, true, false><<<grid, 256, SMEM_BYTES>>>(
            thi, tlo, wthi + WM1T_OFF, wtlo + WM1T_OFF, bm1, mlp,
            nullptr, nullptr, nullptr, nullptr, N_DST1, HID, HID, 0);
    }
    colstat_zero_kernel<<<1, 128>>>();
    colstat_partial_kernel<<<(N_DST1 + 255) / 256, 128>>>(mlp, N_DST1);
    colstat_final_kernel<<<1, 128>>>(N_DST1);
    norm_act_split_kernel<<<(N_DST1 * HID + 255) / 256, 256>>>(mlp, gm, bem, shi, slo, N_DST1, 1);
    {
        dim3 grid((N_DST1 + 127) / 128, (OUT_DIM + 127) / 128);
        mma_gemm2<false, true, false><<<grid, 256, SMEM_BYTES>>>(
            shi, slo, wthi + WM2T_OFF, wtlo + WM2T_OFF, bm2, out,
            nullptr, nullptr, nullptr, nullptr, N_DST1, OUT_DIM, HID, 0);
    }
}

// round 11
// speedup vs baseline: 2.0434x; 1.1543x over previous
#include <cuda_runtime.h>
#include <cuda_bf16.h>
#include <cuda_fp16.h>
#include <cstdint>

#define N_SRC0 120000
#define N_DST0 40000
#define N_DST1 10000
#define T_REL  5
#define HID    128
#define IN_DIM 256
#define OUT_DIM 153
#define E0 800000
#define E1 300000
#define NEG_SLOPE 0.2f
#define EPS_LN 1e-5f

typedef __nv_bfloat16 bf16;

// ---------------- static device scratch ----------------
__device__ __align__(128) __half g_Hs0[(size_t)T_REL * N_SRC0 * HID];
__device__ __align__(128) __half g_Hs1[(size_t)T_REL * N_DST0 * HID];
__device__ __align__(16)  float g_el0[(size_t)T_REL * N_SRC0 * 4];
__device__ __align__(16)  float g_er0[(size_t)T_REL * N_DST0 * 4];
__device__ __align__(16)  float g_el1[(size_t)T_REL * N_DST0 * 4];
__device__ __align__(16)  float g_er1[(size_t)T_REL * N_DST1 * 4];
__device__ __align__(128) float g_acc0[(size_t)N_DST0 * HID];
__device__ __align__(128) float g_acc1[(size_t)N_DST1 * HID];
__device__ __align__(128) float g_mlp[(size_t)N_DST1 * HID];
__device__ int      g_cnt[T_REL * N_DST0];
__device__ int      g_offs[T_REL * (N_DST0 + 1)];
__device__ int      g_cur[T_REL * N_DST0];
__device__ int      g_eperm[T_REL * E0];      // stores SRC node id
__device__ double   g_colsum[HID];
__device__ double   g_colsq[HID];
__device__ float    g_mean[HID];
__device__ float    g_rstd[HID];
__device__ __align__(128) bf16 g_xhi[(size_t)N_SRC0 * IN_DIM];
__device__ __align__(128) bf16 g_xlo[(size_t)N_SRC0 * IN_DIM];
__device__ __align__(128) bf16 g_shi[(size_t)N_DST0 * HID];
__device__ __align__(128) bf16 g_slo[(size_t)N_DST0 * HID];
__device__ __align__(128) bf16 g_thi[(size_t)N_DST1 * HID];
__device__ __align__(128) bf16 g_tlo[(size_t)N_DST1 * HID];
#define W0T_OFF   0
#define WS0T_OFF  163840
#define W1T_OFF   196608
#define WS1T_OFF  278528
#define WM1T_OFF  294912
#define WM2T_OFF  311296
#define WT_TOTAL  330880
__device__ __align__(128) bf16 g_wthi[WT_TOTAL];
__device__ __align__(128) bf16 g_wtlo[WT_TOTAL];

// ---------------- helpers ----------------
__device__ __forceinline__ void cp_async16(uint32_t dst, const void* src, int sz) {
    asm volatile("cp.async.cg.shared.global [%0], [%1], 16, %2;\n"
                 :: "r"(dst), "l"(src), "r"(sz));
}
__device__ __forceinline__ void cp_commit() {
    asm volatile("cp.async.commit_group;\n");
}
__device__ __forceinline__ void ldsm4(uint32_t* r, uint32_t addr) {
    asm volatile("ldmatrix.sync.aligned.m8n8.x4.shared.b16 {%0,%1,%2,%3}, [%4];"
        : "=r"(r[0]), "=r"(r[1]), "=r"(r[2]), "=r"(r[3]) : "r"(addr));
}
__device__ __forceinline__ void mma16816(float* c, const uint32_t* a, uint32_t b0, uint32_t b1) {
    asm volatile("mma.sync.aligned.m16n8k16.row.col.f32.bf16.bf16.f32 "
        "{%0,%1,%2,%3}, {%4,%5,%6,%7}, {%8,%9}, {%0,%1,%2,%3};"
        : "+f"(c[0]), "+f"(c[1]), "+f"(c[2]), "+f"(c[3])
        : "r"(a[0]), "r"(a[1]), "r"(a[2]), "r"(a[3]), "r"(b0), "r"(b1));
}

// ---------------- split kernels ----------------
__global__ void split_kernel(const float* __restrict__ X, bf16* __restrict__ hi,
                             bf16* __restrict__ lo, size_t n)
{
    size_t i = (size_t)blockIdx.x * blockDim.x + threadIdx.x;
    if (i >= n) return;
    float v = X[i];
    bf16 h = __float2bfloat16(v);
    hi[i] = h;
    lo[i] = __float2bfloat16(v - __bfloat162float(h));
}
__global__ void splitw_all_kernel(
    const float* __restrict__ W0, const float* __restrict__ Ws0,
    const float* __restrict__ W1, const float* __restrict__ Ws1,
    const float* __restrict__ Wm1, const float* __restrict__ Wm2,
    bf16* __restrict__ hiT, bf16* __restrict__ loT)
{
    int seg = blockIdx.y;
    const float* W; int K, N, nrel, off;
    switch (seg) {
        case 0:  W = W0;  K = IN_DIM; N = HID;     nrel = T_REL; off = W0T_OFF;  break;
        case 1:  W = Ws0; K = IN_DIM; N = HID;     nrel = 1;     off = WS0T_OFF; break;
        case 2:  W = W1;  K = HID;    N = HID;     nrel = T_REL; off = W1T_OFF;  break;
        case 3:  W = Ws1; K = HID;    N = HID;     nrel = 1;     off = WS1T_OFF; break;
        case 4:  W = Wm1; K = HID;    N = HID;     nrel = 1;     off = WM1T_OFF; break;
        default: W = Wm2; K = HID;    N = OUT_DIM; nrel = 1;     off = WM2T_OFF; break;
    }
    int total = nrel * N * K;
    int idx = blockIdx.x * blockDim.x + threadIdx.x;
    if (idx >= total) return;
    int j = idx / (N * K);
    int rem = idx - j * (N * K);
    int n = rem / K, k = rem - n * K;
    float v = W[((size_t)j * K + k) * N + n];
    bf16 h = __float2bfloat16(v);
    hiT[off + idx] = h;
    loT[off + idx] = __float2bfloat16(v - __bfloat162float(h));
}

// ---------------- fused bf16x3 MMA GEMM (+ optional attn-logit epilogue) ------
#define GSTRIDE  40
#define SM_TILE  (128 * GSTRIDE)
#define SM_AHI   0
#define SM_ALO   SM_TILE
#define SM_BHI   (2 * SM_TILE)
#define SM_BLO   (3 * SM_TILE)
#define SM_STAGE (4 * SM_TILE)
#define SMEM_BYTES (2 * SM_STAGE * 2)

template<bool REL, bool HASBIAS, bool EPI>
__global__ void __launch_bounds__(256, 2) mma_gemm2(
    const bf16* __restrict__ Ahi, const bf16* __restrict__ Alo,
    const bf16* __restrict__ BThi, const bf16* __restrict__ BTlo,
    const float* __restrict__ bias, void* __restrict__ Cv,
    const float* __restrict__ al, const float* __restrict__ ar,
    float* __restrict__ el, float* __restrict__ er,
    int M, int N, int K, int n_er)
{
    extern __shared__ bf16 sm[];

    __half* Ch = (__half*)Cv;
    float*  Cf = (float*)Cv;

    int bm0, bn0, ldc;
    if (REL) {
        int j = blockIdx.x;
        bm0 = blockIdx.y * 128;
        BThi += (size_t)j * 128 * K;
        BTlo += (size_t)j * 128 * K;
        Ch   += (size_t)j * M * 128;
        if (EPI) {
            al += (size_t)j * HID;  ar += (size_t)j * HID;
            el += (size_t)j * M * 4; er += (size_t)j * n_er * 4;
        }
        bn0 = 0; ldc = 128; N = 128;
    } else {
        bm0 = blockIdx.x * 128;
        bn0 = blockIdx.y * 128; ldc = N;
    }

    int tid = threadIdx.x, lane = tid & 31, warp = tid >> 5;
    int wm = (warp & 3) * 32, wn = (warp >> 2) * 64;

    int kc = K >> 5;

    int ldrow = tid >> 2;
    int ldcol = (tid & 3) << 3;

    uint32_t s0 = (uint32_t)__cvta_generic_to_shared(sm);

    int mrowA = lane & 15, mcolA = (lane >> 4) << 3;
    int mrowB = (lane & 7) | ((lane >> 4) << 3);
    int mcolB = ((lane >> 3) & 1) << 3;

    float acc[2][8][4];
#pragma unroll
    for (int a = 0; a < 2; a++)
#pragma unroll
        for (int b = 0; b < 8; b++)
#pragma unroll
            for (int c = 0; c < 4; c++) acc[a][b][c] = 0.f;

#define LOAD_STAGE(IT, ST) do {                                                  \
    int kk_ = (IT) << 5;                                                         \
    uint32_t sb_ = s0 + (uint32_t)(ST) * (SM_STAGE * 2);                         \
    _Pragma("unroll")                                                            \
    for (int hh = 0; hh < 2; hh++) {                                             \
        int row = ldrow + hh * 64;                                               \
        int gm = bm0 + row;                                                      \
        int ok = gm < M;                                                         \
        size_t aoff = (size_t)(ok ? gm : 0) * K + kk_ + ldcol;                   \
        cp_async16(sb_ + (SM_AHI + row * GSTRIDE + ldcol) * 2, Ahi + aoff, ok ? 16 : 0); \
        cp_async16(sb_ + (SM_ALO + row * GSTRIDE + ldcol) * 2, Alo + aoff, ok ? 16 : 0); \
        int gn = bn0 + row;                                                      \
        int okb = gn < N;                                                        \
        size_t boff = (size_t)(okb ? gn : 0) * K + kk_ + ldcol;                  \
        cp_async16(sb_ + (SM_BHI + row * GSTRIDE + ldcol) * 2, BThi + boff, okb ? 16 : 0); \
        cp_async16(sb_ + (SM_BLO + row * GSTRIDE + ldcol) * 2, BTlo + boff, okb ? 16 : 0); \
    }                                                                            \
    cp_commit();                                                                 \
} while (0)

    LOAD_STAGE(0, 0);
    for (int it = 0; it < kc; it++) {
        int st = it & 1;
        if (it + 1 < kc) {
            LOAD_STAGE(it + 1, st ^ 1);
            asm volatile("cp.async.wait_group 1;\n" ::: "memory");
        } else {
            asm volatile("cp.async.wait_group 0;\n" ::: "memory");
        }
        __syncthreads();
        uint32_t base = s0 + (uint32_t)st * (SM_STAGE * 2);
#pragma unroll
        for (int s = 0; s < 2; s++) {
            uint32_t ahi[2][4], alo2[2][4];
#pragma unroll
            for (int mt = 0; mt < 2; mt++) {
                uint32_t ra = (wm + mt * 16 + mrowA) * GSTRIDE + s * 16 + mcolA;
                ldsm4(ahi[mt],  base + (SM_AHI + ra) * 2);
                ldsm4(alo2[mt], base + (SM_ALO + ra) * 2);
            }
#pragma unroll
            for (int np = 0; np < 4; np++) {
                uint32_t bh[4];
                ldsm4(bh, base + (SM_BHI + (wn + np * 16 + mrowB) * GSTRIDE + s * 16 + mcolB) * 2);
#pragma unroll
                for (int mt = 0; mt < 2; mt++) {
                    mma16816(acc[mt][2 * np],     ahi[mt],  bh[0], bh[1]);
                    mma16816(acc[mt][2 * np + 1], ahi[mt],  bh[2], bh[3]);
                    mma16816(acc[mt][2 * np],     alo2[mt], bh[0], bh[1]);
                    mma16816(acc[mt][2 * np + 1], alo2[mt], bh[2], bh[3]);
                }
            }
#pragma unroll
            for (int np = 0; np < 4; np++) {
                uint32_t bl[4];
                ldsm4(bl, base + (SM_BLO + (wn + np * 16 + mrowB) * GSTRIDE + s * 16 + mcolB) * 2);
#pragma unroll
                for (int mt = 0; mt < 2; mt++) {
                    mma16816(acc[mt][2 * np],     ahi[mt], bl[0], bl[1]);
                    mma16816(acc[mt][2 * np + 1], ahi[mt], bl[2], bl[3]);
                }
            }
        }
        __syncthreads();
    }
#undef LOAD_STAGE

    int trow = lane >> 2, tcol = (lane & 3) << 1;
#pragma unroll
    for (int mt = 0; mt < 2; mt++) {
        int gm0 = bm0 + wm + mt * 16 + trow;
        int gm1 = gm0 + 8;
#pragma unroll
        for (int nt = 0; nt < 8; nt++) {
            int gn = bn0 + wn + nt * 8 + tcol;
            float* cr = acc[mt][nt];
            if (REL) {
                if (gm0 < M) {
                    Ch[(size_t)gm0 * ldc + gn]     = __float2half(cr[0]);
                    Ch[(size_t)gm0 * ldc + gn + 1] = __float2half(cr[1]);
                }
                if (gm1 < M) {
                    Ch[(size_t)gm1 * ldc + gn]     = __float2half(cr[2]);
                    Ch[(size_t)gm1 * ldc + gn + 1] = __float2half(cr[3]);
                }
            } else {
                bool okn0 = gn < N, okn1 = gn + 1 < N;
                float b0a = 0.f, b1a = 0.f;
                if (HASBIAS) {
                    if (okn0) b0a = bias[gn];
                    if (okn1) b1a = bias[gn + 1];
                }
                if (gm0 < M) {
                    if (okn0) Cf[(size_t)gm0 * ldc + gn]     = cr[0] + b0a;
                    if (okn1) Cf[(size_t)gm0 * ldc + gn + 1] = cr[1] + b1a;
                }
                if (gm1 < M) {
                    if (okn0) Cf[(size_t)gm1 * ldc + gn]     = cr[2] + b0a;
                    if (okn1) Cf[(size_t)gm1 * ldc + gn + 1] = cr[3] + b1a;
                }
            }
        }
        if (EPI) {
            float eA0 = 0.f, eB0 = 0.f, rA0 = 0.f, rB0 = 0.f;
            float eA1 = 0.f, eB1 = 0.f, rA1 = 0.f, rB1 = 0.f;
#pragma unroll
            for (int nt = 0; nt < 8; nt++) {
                int gn = wn + nt * 8 + tcol;
                float a0v = al[gn], a1v = al[gn + 1];
                float r0v = ar[gn], r1v = ar[gn + 1];
                float* cr = acc[mt][nt];
                float c0 = cr[0] * a0v + cr[1] * a1v;
                float c1 = cr[2] * a0v + cr[3] * a1v;
                float d0 = cr[0] * r0v + cr[1] * r1v;
                float d1 = cr[2] * r0v + cr[3] * r1v;
                if (nt < 4) { eA0 += c0; eA1 += c1; rA0 += d0; rA1 += d1; }
                else        { eB0 += c0; eB1 += c1; rB0 += d0; rB1 += d1; }
            }
#pragma unroll
            for (int d = 1; d < 4; d <<= 1) {
                eA0 += __shfl_xor_sync(0xffffffffu, eA0, d);
                eB0 += __shfl_xor_sync(0xffffffffu, eB0, d);
                rA0 += __shfl_xor_sync(0xffffffffu, rA0, d);
                rB0 += __shfl_xor_sync(0xffffffffu, rB0, d);
                eA1 += __shfl_xor_sync(0xffffffffu, eA1, d);
                eB1 += __shfl_xor_sync(0xffffffffu, eB1, d);
                rA1 += __shfl_xor_sync(0xffffffffu, rA1, d);
                rB1 += __shfl_xor_sync(0xffffffffu, rB1, d);
            }
            if ((lane & 3) == 0) {
                int h0 = wn >> 5;
                if (gm0 < M) {
                    el[(size_t)gm0 * 4 + h0]     = eA0;
                    el[(size_t)gm0 * 4 + h0 + 1] = eB0;
                    if (gm0 < n_er) {
                        er[(size_t)gm0 * 4 + h0]     = rA0;
                        er[(size_t)gm0 * 4 + h0 + 1] = rB0;
                    }
                }
                if (gm1 < M) {
                    el[(size_t)gm1 * 4 + h0]     = eA1;
                    el[(size_t)gm1 * 4 + h0 + 1] = eB1;
                    if (gm1 < n_er) {
                        er[(size_t)gm1 * 4 + h0]     = rA1;
                        er[(size_t)gm1 * 4 + h0 + 1] = rB1;
                    }
                }
            }
        }
    }
}

// ---------------- CSR build ----------------
__global__ void fill_int_kernel(int* p, int n, int v) {
    int i = blockIdx.x * blockDim.x + threadIdx.x;
    if (i < n) p[i] = v;
}
__global__ void hist_kernel(const int* __restrict__ dstAll, int E, int* __restrict__ cnt) {
    int j = blockIdx.y;
    int e = blockIdx.x * blockDim.x + threadIdx.x;
    if (e < E) atomicAdd(&cnt[j * N_DST0 + dstAll[(size_t)j * E + e]], 1);
}
__global__ void scan_kernel(const int* __restrict__ cntAll, int* __restrict__ offsAll,
                            int* __restrict__ curAll, int n) {
    const int* cnt = cntAll + blockIdx.x * N_DST0;
    int* offs = offsAll + blockIdx.x * (N_DST0 + 1);
    int* cur  = curAll + blockIdx.x * N_DST0;
    __shared__ int wsum[32];
    __shared__ int running_s;
    if (threadIdx.x == 0) running_s = 0;
    __syncthreads();
    int lane = threadIdx.x & 31, wid = threadIdx.x >> 5;
    for (int base = 0; base < n; base += 1024) {
        int i = base + (int)threadIdx.x;
        int v = (i < n) ? cnt[i] : 0;
        int x = v;
#pragma unroll
        for (int d = 1; d < 32; d <<= 1) {
            int t = __shfl_up_sync(0xffffffffu, x, d);
            if (lane >= d) x += t;
        }
        if (lane == 31) wsum[wid] = x;
        __syncthreads();
        if (wid == 0) {
            int y = wsum[lane];
#pragma unroll
            for (int d = 1; d < 32; d <<= 1) {
                int t = __shfl_up_sync(0xffffffffu, y, d);
                if (lane >= d) y += t;
            }
            wsum[lane] = y;
        }
        __syncthreads();
        int incl = x + (wid ? wsum[wid - 1] : 0);
        int r = running_s;
        if (i < n) { int o = r + (incl - v); offs[i] = o; cur[i] = o; }
        int total = wsum[31];
        __syncthreads();
        if (threadIdx.x == 0) running_s = r + total;
        __syncthreads();
    }
    if (threadIdx.x == 0) offs[n] = running_s;
}
// scatter storing SRC id (no max pass needed — exp() is overflow-safe here)
__global__ void scatter_kernel(const int* __restrict__ srcAll,
                               const int* __restrict__ dstAll, int E,
                               int* __restrict__ cur, int* __restrict__ eperm)
{
    int j = blockIdx.y;
    int e = blockIdx.x * blockDim.x + threadIdx.x;
    if (e >= E) return;
    int s = srcAll[(size_t)j * E + e];
    int d = dstAll[(size_t)j * E + e];
    int pos = atomicAdd(&cur[j * N_DST0 + d], 1);
    eperm[(size_t)j * E0 + pos] = s;
}

// ---------------- aggregation: one block (64 thr) per (dst, relation) ----------
// Per-relation grid.y keeps the gather working set (one Hs slab) L2-resident.
// Softmax without max-subtraction (logits O(1)); b[j] dropped (cancels in the
// per-column normalization that follows). Merged via float atomicAdd.
__global__ void aggregate_rel_kernel(
    const __half* __restrict__ Hs, int hsrows,
    const float* __restrict__ el, const float* __restrict__ er,
    const int* __restrict__ offs, const int* __restrict__ eperm,
    int n_dst, float* __restrict__ out)
{
    int nd = blockIdx.x;
    int j = blockIdx.y;
    int t = threadIdx.x;              // 0..63, columns 2t, 2t+1
    int h = t >> 4;                   // head of cols 2t,2t+1

    const __half* Hj = Hs + (size_t)j * hsrows * HID;
    const float* elj = el + (size_t)j * hsrows * 4;
    const float* erj = er + (size_t)j * n_dst * 4;
    const int* offj = offs + j * (N_DST0 + 1);
    const int* epj  = eperm + (size_t)j * E0;

    int o0 = offj[nd], o1 = offj[nd + 1];
    int cnt = o1 - o0;
    if (cnt == 0) return;

    __shared__ int   s_src[64];
    __shared__ float s_w[4][64];

    float er_all[4];
    {
        float4 e4 = *(const float4*)(erj + (size_t)nd * 4);
        er_all[0] = e4.x; er_all[1] = e4.y; er_all[2] = e4.z; er_all[3] = e4.w;
    }
    float2 acc = make_float2(0.f, 0.f);
    float ssum = 0.f;
    for (int c0 = 0; c0 < cnt; c0 += 64) {
        int k = c0 + t;
        if (k < cnt) {
            int s = epj[o0 + k];
            s_src[t] = s;
            float4 L = *(const float4*)(elj + (size_t)s * 4);
            float lv[4] = {L.x, L.y, L.z, L.w};
#pragma unroll
            for (int hh = 0; hh < 4; hh++) {
                float v = lv[hh] + er_all[hh];
                v = v > 0.f ? v : NEG_SLOPE * v;
                s_w[hh][t] = __expf(v);
            }
        }
        __syncthreads();
        int len = min(64, cnt - c0);
        const float* wrow = s_w[h];
#pragma unroll 4
        for (int k2 = 0; k2 < len; k2++) {
            float w = wrow[k2];
            __half2 x2 = *(const __half2*)(Hj + (size_t)s_src[k2] * HID + 2 * t);
            float2 xf = __half22float2(x2);
            acc.x += w * xf.x;
            acc.y += w * xf.y;
            ssum += w;
        }
        __syncthreads();
    }
    float inv = 1.f / ssum;
    float* op = out + (size_t)nd * HID + 2 * t;
    atomicAdd(op,     acc.x * inv);
    atomicAdd(op + 1, acc.y * inv);
}

// ---------------- column norm + activation ----------------
__global__ void colstat_zero_kernel() {
    int t = threadIdx.x;
    g_colsum[t] = 0.0; g_colsq[t] = 0.0;
}
__global__ void colstat_partial_kernel(const float* __restrict__ X, int nrows) {
    int t = threadIdx.x;
    int r0 = blockIdx.x * 256;
    int r1 = min(r0 + 256, nrows);
    float fs = 0.f, fq = 0.f;
    for (int r = r0; r < r1; r++) {
        float v = X[(size_t)r * HID + t];
        fs += v; fq += v * v;
    }
    atomicAdd(&g_colsum[t], (double)fs);
    atomicAdd(&g_colsq[t], (double)fq);
}
__global__ void colstat_final_kernel(int nrows) {
    int t = threadIdx.x;
    double inv = 1.0 / (double)nrows;
    double mean = g_colsum[t] * inv;
    double var = g_colsq[t] * inv - mean * mean;
    g_mean[t] = (float)mean;
    g_rstd[t] = (float)(1.0 / sqrt(var + (double)EPS_LN));
}
__global__ void norm_act_split_kernel(const float* __restrict__ X,
                                      const float* __restrict__ g,
                                      const float* __restrict__ be,
                                      bf16* __restrict__ hi, bf16* __restrict__ lo,
                                      int nrows, int act)
{
    int idx = blockIdx.x * blockDim.x + threadIdx.x;
    if (idx >= nrows * HID) return;
    int t = idx & (HID - 1);
    float v = (X[idx] - g_mean[t]) * g_rstd[t] * g[t] + be[t];
    if (act) v = v > 0.f ? v : 0.f;
    else     v = v > 0.f ? v : expm1f(v);
    bf16 h = __float2bfloat16(v);
    hi[idx] = h;
    lo[idx] = __float2bfloat16(v - __bfloat162float(h));
}

// ---------------- host orchestration ----------------
static inline void* sym(const void* s) { void* p = nullptr; cudaGetSymbolAddress(&p, s); return p; }

static void set_smem_attrs() {
    cudaFuncSetAttribute(mma_gemm2<true,  false, true >, cudaFuncAttributeMaxDynamicSharedMemorySize, SMEM_BYTES);
    cudaFuncSetAttribute(mma_gemm2<false, true,  false>, cudaFuncAttributeMaxDynamicSharedMemorySize, SMEM_BYTES);
}

static void run_layer(const bf16* Ahi, const bf16* Alo, int n_src, int n_dst, int Kdim,
                      const bf16* WtHi, const bf16* WtLo,
                      const bf16* WsHi, const bf16* WsLo,
                      const float* alpha_l, const float* alpha_r,
                      const float* bs,
                      const float* gamma, const float* beta,
                      const int* srcAll, const int* dstAll, int E,
                      __half* Hs, float* elbuf, float* erbuf,
                      float* accbuf, bf16* outhi, bf16* outlo)
{
    int* cnt = (int*)sym(g_cnt);
    int* offs = (int*)sym(g_offs);
    int* cur = (int*)sym(g_cur);
    int* eperm = (int*)sym(g_eperm);

    fill_int_kernel<<<(T_REL * N_DST0 + 255) / 256, 256>>>(cnt, T_REL * N_DST0, 0);

    {   // Hs = A @ W[j]^T for all relations (grid.x = relation for A-tile L2 reuse)
        dim3 grid(T_REL, (n_src + 127) / 128);
        mma_gemm2<true, false, true><<<grid, 256, SMEM_BYTES>>>(
            Ahi, Alo, WtHi, WtLo, nullptr, Hs,
            alpha_l, alpha_r, elbuf, erbuf, n_src, HID, Kdim, n_dst);
    }

    { dim3 grid((E + 255) / 256, T_REL);
      hist_kernel<<<grid, 256>>>(dstAll, E, cnt); }
    scan_kernel<<<T_REL, 1024>>>(cnt, offs, cur, n_dst);
    { dim3 grid((E + 255) / 256, T_REL);
      scatter_kernel<<<grid, 256>>>(srcAll, dstAll, E, cur, eperm); }

    {   // acc = A[:n_dst] @ Ws + bs (fp32 out)
        dim3 grid((n_dst + 127) / 128, 1);
        mma_gemm2<false, true, false><<<grid, 256, SMEM_BYTES>>>(
            Ahi, Alo, WsHi, WsLo, bs, accbuf,
            nullptr, nullptr, nullptr, nullptr, n_dst, HID, Kdim, 0);
    }

    { dim3 grid(n_dst, T_REL);
      aggregate_rel_kernel<<<grid, 64>>>(Hs, n_src, elbuf, erbuf, offs, eperm,
                                         n_dst, accbuf); }

    colstat_zero_kernel<<<1, 128>>>();
    colstat_partial_kernel<<<(n_dst + 255) / 256, 128>>>(accbuf, n_dst);
    colstat_final_kernel<<<1, 128>>>(n_dst);
    norm_act_split_kernel<<<(n_dst * HID + 255) / 256, 256>>>(accbuf, gamma, beta,
                                                              outhi, outlo, n_dst, 0);
}

extern "C" void kernel_launch(void* const* d_in, const int* in_sizes, int n_in,
                              void* d_out, int out_size)
{
    (void)in_sizes; (void)n_in; (void)out_size;
    const float* x   = (const float*)d_in[0];
    const float* W0  = (const float*)d_in[1];
    const float* al0 = (const float*)d_in[2];
    const float* ar0 = (const float*)d_in[3];
    const float* Ws0 = (const float*)d_in[5];
    const float* bs0 = (const float*)d_in[6];
    const float* g0  = (const float*)d_in[7];
    const float* be0 = (const float*)d_in[8];
    const float* W1  = (const float*)d_in[9];
    const float* al1 = (const float*)d_in[10];
    const float* ar1 = (const float*)d_in[11];
    const float* Ws1 = (const float*)d_in[13];
    const float* bs1 = (const float*)d_in[14];
    const float* g1  = (const float*)d_in[15];
    const float* be1 = (const float*)d_in[16];
    const float* Wm1 = (const float*)d_in[17];
    const float* bm1 = (const float*)d_in[18];
    const float* gm  = (const float*)d_in[19];
    const float* bem = (const float*)d_in[20];
    const float* Wm2 = (const float*)d_in[21];
    const float* bm2 = (const float*)d_in[22];
    const int* src0  = (const int*)d_in[23];
    const int* dst0  = (const int*)d_in[24];
    const int* src1  = (const int*)d_in[25];
    const int* dst1  = (const int*)d_in[26];
    float* out = (float*)d_out;

    __half* Hs0 = (__half*)sym(g_Hs0);
    __half* Hs1 = (__half*)sym(g_Hs1);
    float* el0p = (float*)sym(g_el0);
    float* er0p = (float*)sym(g_er0);
    float* el1p = (float*)sym(g_el1);
    float* er1p = (float*)sym(g_er1);
    float* acc0 = (float*)sym(g_acc0);
    float* acc1 = (float*)sym(g_acc1);
    float* mlp  = (float*)sym(g_mlp);
    bf16* xhi = (bf16*)sym(g_xhi);
    bf16* xlo = (bf16*)sym(g_xlo);
    bf16* shi = (bf16*)sym(g_shi);
    bf16* slo = (bf16*)sym(g_slo);
    bf16* thi = (bf16*)sym(g_thi);
    bf16* tlo = (bf16*)sym(g_tlo);
    bf16* wthi = (bf16*)sym(g_wthi);
    bf16* wtlo = (bf16*)sym(g_wtlo);

    set_smem_attrs();

    {
        dim3 g((T_REL * HID * IN_DIM + 255) / 256, 6);
        splitw_all_kernel<<<g, 256>>>(W0, Ws0, W1, Ws1, Wm1, Wm2, wthi, wtlo);
    }
    {
        size_t n = (size_t)N_SRC0 * IN_DIM;
        split_kernel<<<(unsigned)((n + 255) / 256), 256>>>(x, xhi, xlo, n);
    }

    // Layer 0
    run_layer(xhi, xlo, N_SRC0, N_DST0, IN_DIM,
              wthi + W0T_OFF, wtlo + W0T_OFF, wthi + WS0T_OFF, wtlo + WS0T_OFF,
              al0, ar0, bs0, g0, be0,
              src0, dst0, E0, Hs0, el0p, er0p, acc0, shi, slo);

    // Layer 1
    run_layer(shi, slo, N_DST0, N_DST1, HID,
              wthi + W1T_OFF, wtlo + W1T_OFF, wthi + WS1T_OFF, wtlo + WS1T_OFF,
              al1, ar1, bs1, g1, be1,
              src1, dst1, E1, Hs1, el1p, er1p, acc1, thi, tlo);

    // MLP
    {
        dim3 grid((N_DST1 + 127) / 128, 1);
        mma_gemm2<false, true, false><<<grid, 256, SMEM_BYTES>>>(
            thi, tlo, wthi + WM1T_OFF, wtlo + WM1T_OFF, bm1, mlp,
            nullptr, nullptr, nullptr, nullptr, N_DST1, HID, HID, 0);
    }
    colstat_zero_kernel<<<1, 128>>>();
    colstat_partial_kernel<<<(N_DST1 + 255) / 256, 128>>>(mlp, N_DST1);
    colstat_final_kernel<<<1, 128>>>(N_DST1);
    norm_act_split_kernel<<<(N_DST1 * HID + 255) / 256, 256>>>(mlp, gm, bem, shi, slo, N_DST1, 1);
    {
        dim3 grid((N_DST1 + 127) / 128, (OUT_DIM + 127) / 128);
        mma_gemm2<false, true, false><<<grid, 256, SMEM_BYTES>>>(
            shi, slo, wthi + WM2T_OFF, wtlo + WM2T_OFF, bm2, out,
            nullptr, nullptr, nullptr, nullptr, N_DST1, OUT_DIM, HID, 0);
    }
}